// round 9
// baseline (speedup 1.0000x reference)
#include <cuda_runtime.h>
#include <math.h>
#include <float.h>

#define Bn    8
#define Hn    96
#define Wn    96
#define HWn   9216
#define FCn   768
#define Rn    12
#define Pn    16
#define KSn   13
#define TOPKn 24

typedef unsigned long long ull;

// ---------------- scratch (device globals) ----------------
__device__ float g_t1[Bn*Rn*HWn];
__device__ float g_proj[Bn*Rn*HWn];
__device__ float g_canvas[Bn*Rn*HWn];
__device__ float g_occraw[Bn*HWn];
__device__ float g_cavg[Bn*HWn];
__device__ float g_sup[Bn*HWn];
__device__ float g_occ[Bn*HWn];
__device__ float g_dnorm[Bn*HWn];
__device__ float g_anch[Bn*HWn];
__device__ unsigned g_umn[24], g_umx[24];   // [0..7] occraw, [8..15] density, [16..23] cavg
__device__ int   g_ncand[Bn];
__device__ float g_cand_v[Bn*HWn];
__device__ int   g_cand_i[Bn*HWn];

// ---------------- helpers ----------------
__device__ __forceinline__ void ffma2(ull &acc, ull a, ull b) {
    asm("fma.rn.f32x2 %0, %1, %2, %0;" : "+l"(acc) : "l"(a), "l"(b));
}
__device__ __forceinline__ ull dup2(float x) {
    ull r;
    asm("mov.b64 %0, {%1, %1};" : "=l"(r) : "f"(x));
    return r;
}
__device__ __forceinline__ float2 unpack2(ull v) {
    float2 r;
    asm("mov.b64 {%0, %1}, %2;" : "=f"(r.x), "=f"(r.y) : "l"(v));
    return r;
}
__device__ __forceinline__ float gelu_exact(float x) {
    return 0.5f * x * (1.0f + erff(x * 0.70710678118654752440f));
}

// padded-tile stencils: storage col of global x is x+1, row stride 100
__device__ __forceinline__ float pmax3(const float* S, int cr, int x) {
    const float* p = S + (cr - 1) * 100 + x;
    float a = fmaxf(fmaxf(p[0],   p[1]),   p[2]);
    float b = fmaxf(fmaxf(p[100], p[101]), p[102]);
    float c = fmaxf(fmaxf(p[200], p[201]), p[202]);
    return fmaxf(a, fmaxf(b, c));
}
__device__ __forceinline__ float pmin3(const float* S, int cr, int x) {
    const float* p = S + (cr - 1) * 100 + x;
    float a = fminf(fminf(p[0],   p[1]),   p[2]);
    float b = fminf(fminf(p[100], p[101]), p[102]);
    float c = fminf(fminf(p[200], p[201]), p[202]);
    return fminf(a, fminf(b, c));
}
__device__ __forceinline__ float psum3(const float* S, int cr, int x) {
    const float* p = S + (cr - 1) * 100 + x;
    return p[0] + p[1] + p[2] + p[100] + p[101] + p[102] + p[200] + p[201] + p[202];
}

// ---------------- K_init: reset stats + candidate counters ----------------
__global__ void k_init() {
    int t = threadIdx.x;
    if (t < 24) { g_umn[t] = 0x7f800000u; g_umx[t] = 0u; }
    if (t >= 32 && t < 32 + Bn) g_ncand[t - 32] = 0;
}

// ---------------- K1: conv1x1 FC->R + gelu (3-buffer deep LDG pipeline) ----------------
__global__ void __launch_bounds__(256, 2) k_conv1(const float* __restrict__ feat,
                                                  const float* __restrict__ w1,
                                                  const float* __restrict__ b1) {
    __shared__ __align__(16) float sw[FCn*Rn];
    for (int i = threadIdx.x; i < FCn*Rn; i += 256) {
        int c = i / Rn, r = i - c*Rn;
        sw[i] = w1[r*FCn + c];
    }
    __syncthreads();
    int b = blockIdx.x / 36;
    int p = (blockIdx.x % 36) * 256 + threadIdx.x;
    const float* fb = feat + (size_t)b * FCn * HWn + p;

    ull acc[6];
#pragma unroll
    for (int j = 0; j < 6; j++) acc[j] = 0ull;

    const ulonglong2* wv = (const ulonglong2*)sw;

#define LOAD8(X, CH) do { \
    _Pragma("unroll") \
    for (int u_ = 0; u_ < 8; u_++) X[u_] = fb[(size_t)((CH) + u_) * HWn]; \
} while (0)
#define COMP8(X, CH) do { \
    _Pragma("unroll") \
    for (int u_ = 0; u_ < 8; u_++) { \
        ull d_ = dup2(X[u_]); \
        const ulonglong2* w_ = wv + ((CH) + u_) * 3; \
        ulonglong2 q0 = w_[0], q1 = w_[1], q2 = w_[2]; \
        ffma2(acc[0], d_, q0.x); ffma2(acc[1], d_, q0.y); \
        ffma2(acc[2], d_, q1.x); ffma2(acc[3], d_, q1.y); \
        ffma2(acc[4], d_, q2.x); ffma2(acc[5], d_, q2.y); \
    } \
} while (0)

    float A[8], B[8], C[8];
    LOAD8(A, 0); LOAD8(B, 8); LOAD8(C, 16);
    int cb = 0;
#pragma unroll 1
    for (int it = 0; it < 31; it++) {
        COMP8(A, cb);      LOAD8(A, cb + 24);
        COMP8(B, cb + 8);  LOAD8(B, cb + 32);
        COMP8(C, cb + 16); LOAD8(C, cb + 40);
        cb += 24;
    }
    COMP8(A, 744); COMP8(B, 752); COMP8(C, 760);
#undef LOAD8
#undef COMP8

    float* op = g_t1 + (size_t)b * Rn * HWn + p;
#pragma unroll
    for (int j = 0; j < 6; j++) {
        float2 a = unpack2(acc[j]);
        op[(size_t)(2*j)     * HWn] = gelu_exact(a.x + __ldg(b1 + 2*j));
        op[(size_t)(2*j + 1) * HWn] = gelu_exact(a.y + __ldg(b1 + 2*j + 1));
    }
}

// ---------------- K2: conv3x3 R->R + gelu + occ_raw + canvas zero ----------------
__global__ void __launch_bounds__(256) k_conv2(const float* __restrict__ w2,
                                               const float* __restrict__ b2) {
    __shared__ float tile[Rn][18*18];
    __shared__ __align__(16) float sw2[Rn*Rn*9];
    __shared__ __align__(16) float sb2[Rn];
    int b   = blockIdx.z;
    int ty0 = blockIdx.y * 16, tx0 = blockIdx.x * 16;
    for (int i = threadIdx.x; i < Rn*Rn*9; i += 256) {
        int rout = i % 12;
        int rest = i / 12;
        int rin  = rest / 9;
        int k9   = rest % 9;
        sw2[i] = w2[(rout*12 + rin) * 9 + k9];
    }
    if (threadIdx.x < Rn) sb2[threadIdx.x] = b2[threadIdx.x];
    const float* tin = g_t1 + (size_t)b * Rn * HWn;
    for (int i = threadIdx.x; i < Rn*324; i += 256) {
        int ch = i / 324, rem = i - ch*324;
        int yy = rem / 18, xx = rem % 18;
        int gy = ty0 + yy - 1, gx = tx0 + xx - 1;
        float v = 0.0f;
        if (gy >= 0 && gy < Hn && gx >= 0 && gx < Wn)
            v = tin[(size_t)ch * HWn + gy*Wn + gx];
        tile[ch][rem] = v;
    }
    __syncthreads();
    int ty = threadIdx.x / 16, tx = threadIdx.x % 16;
    ull acc[6];
    {
        const ull* bb = (const ull*)sb2;
#pragma unroll
        for (int j = 0; j < 6; j++) acc[j] = bb[j];
    }
    const ulonglong2* wv = (const ulonglong2*)sw2;
#pragma unroll
    for (int rin = 0; rin < 12; rin++) {
#pragma unroll
        for (int k9 = 0; k9 < 9; k9++) {
            int ky = k9 / 3, kx = k9 % 3;
            ull d = dup2(tile[rin][(ty + ky)*18 + tx + kx]);
            const ulonglong2* w = wv + (rin*9 + k9) * 3;
            ulonglong2 w0 = w[0], w1v = w[1], w2v = w[2];
            ffma2(acc[0], d, w0.x);  ffma2(acc[1], d, w0.y);
            ffma2(acc[2], d, w1v.x); ffma2(acc[3], d, w1v.y);
            ffma2(acc[4], d, w2v.x); ffma2(acc[5], d, w2v.y);
        }
    }
    int p = (ty0 + ty)*Wn + tx0 + tx;
    float* pout = g_proj + (size_t)b * Rn * HWn + p;
    float* cz   = g_canvas + (size_t)b * Rn * HWn + p;
    float asum = 0.0f;
#pragma unroll
    for (int j = 0; j < 6; j++) {
        float2 a = unpack2(acc[j]);
        float g0 = gelu_exact(a.x), g1 = gelu_exact(a.y);
        pout[(size_t)(2*j)     * HWn] = g0;
        pout[(size_t)(2*j + 1) * HWn] = g1;
        cz[(size_t)(2*j)     * HWn] = 0.0f;
        cz[(size_t)(2*j + 1) * HWn] = 0.0f;
        asum += fabsf(g0) + fabsf(g1);
    }
    g_occraw[b*HWn + p] = asum * (1.0f / 12.0f);
}

// ---------------- K_pre: cavg + per-batch min/max stats (96 blocks) ----------------
__global__ void __launch_bounds__(256) k_pre(const float* __restrict__ carrier,
                                             const float* __restrict__ density) {
    __shared__ float C[10*100];
    int blk = blockIdx.x;
    int b   = blk / 12;
    int r0  = (blk % 12) * 8;
    const size_t base = (size_t)b * HWn;
    int tid = threadIdx.x, lane = tid & 31;

    for (int i = tid; i < 10*100; i += 256) C[i] = 0.0f;
    __syncthreads();
    for (int i = tid; i < 10*96; i += 256) {
        int rr = i / 96, x = i - rr*96;
        int gr = r0 - 1 + rr;
        if (gr >= 0 && gr < Hn)
            C[rr*100 + 1 + x] = fabsf(carrier[base + gr*Wn + x]);
    }
    __syncthreads();

    float cmn = FLT_MAX, cmx = 0.0f;
    float dmn = FLT_MAX, dmx = 0.0f;
    float omn = FLT_MAX, omx = 0.0f;
    for (int i = tid; i < 8*96; i += 256) {
        int rr = i / 96, x = i - rr*96;
        int gr = r0 + rr;
        float cv = psum3(C, rr + 1, x) * (1.0f / 9.0f);
        g_cavg[base + gr*Wn + x] = cv;
        cmn = fminf(cmn, cv); cmx = fmaxf(cmx, cv);
        float d = density[base + gr*Wn + x];
        dmn = fminf(dmn, d); dmx = fmaxf(dmx, d);
        float o = g_occraw[base + gr*Wn + x];
        omn = fminf(omn, o); omx = fmaxf(omx, o);
    }
#pragma unroll
    for (int off = 16; off; off >>= 1) {
        cmn = fminf(cmn, __shfl_xor_sync(0xffffffffu, cmn, off));
        cmx = fmaxf(cmx, __shfl_xor_sync(0xffffffffu, cmx, off));
        dmn = fminf(dmn, __shfl_xor_sync(0xffffffffu, dmn, off));
        dmx = fmaxf(dmx, __shfl_xor_sync(0xffffffffu, dmx, off));
        omn = fminf(omn, __shfl_xor_sync(0xffffffffu, omn, off));
        omx = fmaxf(omx, __shfl_xor_sync(0xffffffffu, omx, off));
    }
    if (!lane) {
        atomicMin(&g_umn[b],      __float_as_uint(omn));
        atomicMax(&g_umx[b],      __float_as_uint(omx));
        atomicMin(&g_umn[8 + b],  __float_as_uint(dmn));
        atomicMax(&g_umx[8 + b],  __float_as_uint(dmx));
        atomicMin(&g_umn[16 + b], __float_as_uint(cmn));
        atomicMax(&g_umx[16 + b], __float_as_uint(cmx));
    }
}

// ---------------- K_morph: mask->erode->open->sup->scores->NMS, tiled (96 blocks) ----------------
__global__ void __launch_bounds__(256) k_morph(const float* __restrict__ density) {
    __shared__ float A[16*100];
    __shared__ float Bf[16*100];
    int blk = blockIdx.x;
    int b   = blk / 12;
    int r0  = (blk % 12) * 8;
    const size_t base = (size_t)b * HWn;
    int tid = threadIdx.x, lane = tid & 31;

    float omn = __uint_as_float(g_umn[b]),      omx = __uint_as_float(g_umx[b]);
    float dmn = __uint_as_float(g_umn[8 + b]),  dmx = __uint_as_float(g_umx[8 + b]);
    float cmn = __uint_as_float(g_umn[16 + b]), cmx = __uint_as_float(g_umx[16 + b]);
    float oinv = 1.0f / fmaxf(omx - omn, 1e-6f);
    float dinv = 1.0f / fmaxf(dmx - dmn, 1e-6f);
    float cinv = 1.0f / fmaxf(cmx - cmn, 1e-6f);

    // P_mask -> A (identity +inf for erode)
    for (int i = tid; i < 16*96; i += 256) {
        int cr = i / 96, x = i - cr*96;
        int gr = r0 - 4 + cr;
        float v = FLT_MAX;
        if (gr >= 0 && gr < Hn) {
            float cs = (g_cavg[base + gr*Wn + x] - cmn) * cinv;
            float dn = (density[base + gr*Wn + x] - dmn) * dinv;
            float ev = 0.8f * cs + 0.2f * dn;
            v = (ev >= 0.28f) ? 1.0f : 0.0f;
        }
        A[cr*100 + 1 + x] = v;
    }
    if (tid < 32) A[(tid >> 1)*100 + ((tid & 1) ? 97 : 0)] = FLT_MAX;
    __syncthreads();

    // P_erode -> Bf (identity 0 for max)
    for (int i = tid; i < 16*96; i += 256) {
        int cr = i / 96, x = i - cr*96;
        int gr = r0 - 4 + cr;
        float v = 0.0f;
        if (cr >= 1 && cr < 15 && gr >= 0 && gr < Hn)
            v = pmin3(A, cr, x);
        Bf[cr*100 + 1 + x] = v;
    }
    if (tid < 32) Bf[(tid >> 1)*100 + ((tid & 1) ? 97 : 0)] = 0.0f;
    __syncthreads();

    // P_open (dilate of erode) -> A
    for (int i = tid; i < 16*96; i += 256) {
        int cr = i / 96, x = i - cr*96;
        int gr = r0 - 4 + cr;
        float v = 0.0f;
        if (cr >= 2 && cr < 14 && gr >= 0 && gr < Hn)
            v = fminf(fmaxf(pmax3(Bf, cr, x), 0.0f), 1.0f);
        A[cr*100 + 1 + x] = v;
    }
    if (tid < 32) A[(tid >> 1)*100 + ((tid & 1) ? 97 : 0)] = 0.0f;
    __syncthreads();

    // P_sup (dilate) + scores -> Bf ; write sup/occ/dnorm/anch for own rows
    for (int i = tid; i < 16*96; i += 256) {
        int cr = i / 96, x = i - cr*96;
        int gr = r0 - 4 + cr;
        float v = 0.0f;
        if (cr >= 3 && cr < 13 && gr >= 0 && gr < Hn) {
            float sp = fminf(fmaxf(pmax3(A, cr, x), 0.0f), 1.0f);
            float oc = (g_occraw[base + gr*Wn + x] - omn) * oinv;
            v = oc * sp;
            if (cr >= 4 && cr < 12) {
                g_sup[base + gr*Wn + x] = sp;
                g_occ[base + gr*Wn + x] = oc;
                g_dnorm[base + gr*Wn + x] = (density[base + gr*Wn + x] - dmn) * dinv;
                g_anch[base + gr*Wn + x] = 0.0f;
            }
        }
        Bf[cr*100 + 1 + x] = v;
    }
    if (tid < 32) Bf[(tid >> 1)*100 + ((tid & 1) ? 97 : 0)] = 0.0f;
    __syncthreads();

    // P_nms over own rows + candidate compaction
    for (int i = tid; i < 8*96; i += 256) {
        int rr = i / 96, x = i - rr*96;
        int cr = 4 + rr;
        float sc = Bf[cr*100 + 1 + x];
        float lm = pmax3(Bf, cr, x);
        bool peak = (sc >= lm) && (sc > 0.05f);
        unsigned bal = __ballot_sync(0xffffffffu, peak);
        if (bal) {
            int leader = __ffs((int)bal) - 1;
            int cnt  = __popc(bal);
            int pref = __popc(bal & ((1u << lane) - 1u));
            int basePos = 0;
            if (lane == leader) basePos = atomicAdd(&g_ncand[b], cnt);
            basePos = __shfl_sync(0xffffffffu, basePos, leader);
            if (peak) {
                int pos = basePos + pref;
                g_cand_v[b*HWn + pos] = sc;
                g_cand_i[b*HWn + pos] = (r0 + rr)*Wn + x;
            }
        }
    }
}

// ---------------- K_sel: top-24 + proto argmax + stamping (8 blocks) ----------------
__device__ __constant__ float c_lenL[4] = {0.4f, 0.7f, 1.0f, 1.25f};
__device__ __constant__ float c_widL[4] = {0.12f, 0.18f, 0.24f, 0.3f};

#define SELCAP 5120

__global__ void __launch_bounds__(1024) k_sel(const float* __restrict__ proto) {
    __shared__ float scv[SELCAP];
    __shared__ int   sci[SELCAP];
    __shared__ float sprot[Pn*Rn];
    __shared__ float s_val[TOPKn];
    __shared__ int   s_idx[TOPKn];
    __shared__ int   spidx[TOPKn];

    int b = blockIdx.x, tid = threadIdx.x;
    int lane = tid & 31, warp = tid >> 5;
    const size_t base = (size_t)b * HWn;

    if (tid < Pn*Rn) sprot[tid] = proto[tid];
    int nc = g_ncand[b];
    bool smem_path = (nc <= SELCAP);
    if (smem_path) {
        for (int i = tid; i < nc; i += 1024) {
            scv[i] = g_cand_v[b*HWn + i];
            sci[i] = g_cand_i[b*HWn + i];
        }
    }
    __syncthreads();

    if (warp == 0) {
        float* cvv = smem_path ? scv : (g_cand_v + b*HWn);
        int*   cii = smem_path ? sci : (g_cand_i + b*HWn);
        for (int k = 0; k < TOPKn; k++) {
            float v = -FLT_MAX; int bi = 0x7fffffff; int bp = -1;
            for (int p = lane; p < nc; p += 32) {
                float m = cvv[p]; int ix = cii[p];
                if (m > v || (m == v && ix < bi)) { v = m; bi = ix; bp = p; }
            }
            float myv = v; int mybi = bi;
#pragma unroll
            for (int off = 16; off; off >>= 1) {
                float ov = __shfl_xor_sync(0xffffffffu, v, off);
                int   oi = __shfl_xor_sync(0xffffffffu, bi, off);
                if (ov > v || (ov == v && oi < bi)) { v = ov; bi = oi; }
            }
            if (v > 0.0f && myv == v && mybi == bi && bp >= 0)
                cvv[bp] = -FLT_MAX;
            if (!smem_path) __threadfence_block();
            __syncwarp();
            if (!lane) {
                if (v > 0.0f) { s_val[k] = v;    s_idx[k] = bi; }
                else          { s_val[k] = 0.0f; s_idx[k] = -1; }
            }
        }
    }
    __syncthreads();

    if (tid < TOPKn) {
        float v = s_val[tid];
        int   ix = s_idx[tid];
        if (v > 0.0f && ix >= 0) {
            g_anch[base + ix] = v;
            float f[Rn];
#pragma unroll
            for (int r = 0; r < Rn; r++)
                f[r] = g_proj[((size_t)b*Rn + r) * HWn + ix];
            float best = -FLT_MAX; int bp = 0;
#pragma unroll
            for (int p = 0; p < Pn; p++) {
                float l = 0.0f;
#pragma unroll
                for (int r = 0; r < Rn; r++) l += f[r] * sprot[p*Rn + r];
                if (l > best) { best = l; bp = p; }
            }
            spidx[tid] = bp;
        } else {
            spidx[tid] = 0;
        }
    }
    __syncthreads();

    for (int wk = tid; wk < TOPKn * KSn * KSn; wk += 1024) {
        int a = wk / (KSn*KSn);
        int t = wk - a * (KSn*KSn);
        float val = s_val[a];
        if (val <= 0.0f) continue;
        int idx = s_idx[a];
        int pi  = spidx[a];
        int ys = idx / Wn, xs = idx % Wn;
        int dy = t / KSn, dx = t % KSn;
        int y = ys + dy - KSn/2, x = xs + dx - KSn/2;
        if (y < 0 || y >= Hn || x < 0 || x >= Wn) continue;
        float gx  = (float)(-1.0 + (double)dx * (2.0 / 12.0));
        float gy  = (float)(-1.0 + (double)dy * (2.0 / 12.0));
        float ori = (float)((double)pi * (3.14159265358979323846 / 16.0));
        float ln  = c_lenL[pi & 3];
        float wd  = c_widL[(pi >> 2) & 3];
        float c = cosf(ori), s = sinf(ori);
        float xr =  c * gx + s * gy;
        float yr = -s * gx + c * gy;
        float txx = xr / ln, tyy = yr / wd;
        float foot = expf(-(txx*txx) - (tyy*tyy)) * val;
        float* cvp = g_canvas + (size_t)b * Rn * HWn + y*Wn + x;
#pragma unroll
        for (int r = 0; r < Rn; r++)
            atomicAdd(cvp + (size_t)r * HWn, sprot[pi*Rn + r] * foot);
    }
}

// ---------------- final: (16->12 gelu)->(12->768), f-split x2, 4 acc chains ----------------
__global__ void __launch_bounds__(128) k_final(const float* __restrict__ w3,
                                               const float* __restrict__ b3,
                                               const float* __restrict__ w4,
                                               const float* __restrict__ b4,
                                               float* __restrict__ outp) {
    __shared__ __align__(16) ull wint[192*12];
    __shared__ ull bp4[192];
    __shared__ float sw3[Rn*16];
    __shared__ float sb3[Rn];

    int bx = blockIdx.x;
    int fh = bx & 1;
    int t2 = bx >> 1;
    int b  = t2 / 36;
    int f0 = fh * 384;
    {
        float* wf = (float*)wint;
        for (int i = threadIdx.x; i < 384*Rn; i += 128) {
            int fl = i / Rn, r = i - fl*Rn;
            wf[(fl >> 1)*24 + r*2 + (fl & 1)] = w4[(f0 + fl)*Rn + r];
        }
        float* bf = (float*)bp4;
        for (int i = threadIdx.x; i < 384; i += 128) bf[i] = b4[f0 + i];
        for (int i = threadIdx.x; i < Rn*16; i += 128) sw3[i] = w3[i];
        for (int i = threadIdx.x; i < Rn;    i += 128) sb3[i] = b3[i];
    }
    __syncthreads();

    int p0 = (t2 % 36) * 256 + threadIdx.x * 2;
    size_t bpx = (size_t)b * HWn + p0;

    float2 sup = *(const float2*)(g_sup + bpx);
    float2 occ = *(const float2*)(g_occ + bpx);
    float2 an  = *(const float2*)(g_anch + bpx);
    float2 dn  = *(const float2*)(g_dnorm + bpx);

    float in0[16], in1[16];
#pragma unroll
    for (int r = 0; r < Rn; r++) {
        float2 cv = *(const float2*)(g_canvas + ((size_t)b*Rn + r) * HWn + p0);
        in0[r] = cv.x * sup.x;
        in1[r] = cv.y * sup.y;
    }
    in0[12] = occ.x; in1[12] = occ.y;
    in0[13] = sup.x; in1[13] = sup.y;
    in0[14] = an.x;  in1[14] = an.y;
    in0[15] = dn.x;  in1[15] = dn.y;

    ull md0[Rn], md1[Rn];
#pragma unroll
    for (int r = 0; r < Rn; r++) {
        float m0 = sb3[r], m1 = sb3[r];
#pragma unroll
        for (int j = 0; j < 16; j++) {
            float w = sw3[r*16 + j];
            m0 += in0[j] * w;
            m1 += in1[j] * w;
        }
        md0[r] = dup2(gelu_exact(m0));
        md1[r] = dup2(gelu_exact(m1));
    }

    float* ob = outp + (size_t)b * FCn * HWn + (size_t)f0 * HWn + p0;
    const ulonglong2* wv = (const ulonglong2*)wint;
#pragma unroll 2
    for (int fp = 0; fp < 192; fp += 2) {
        ull a0 = bp4[fp];
        ull a1 = a0;
        ull a2 = bp4[fp + 1];
        ull a3 = a2;
        const ulonglong2* w = wv + fp*6;
#pragma unroll
        for (int q = 0; q < 6; q++) {
            ulonglong2 wq = w[q];
            ulonglong2 w2 = w[q + 6];
            ffma2(a0, md0[2*q],     wq.x);
            ffma2(a1, md1[2*q],     wq.x);
            ffma2(a2, md0[2*q],     w2.x);
            ffma2(a3, md1[2*q],     w2.x);
            ffma2(a0, md0[2*q + 1], wq.y);
            ffma2(a1, md1[2*q + 1], wq.y);
            ffma2(a2, md0[2*q + 1], w2.y);
            ffma2(a3, md1[2*q + 1], w2.y);
        }
        float2 u0 = unpack2(a0), u1 = unpack2(a1);
        float2 u2 = unpack2(a2), u3 = unpack2(a3);
        float2 v0; v0.x = u0.x; v0.y = u1.x;
        float2 v1; v1.x = u0.y; v1.y = u1.y;
        float2 v2; v2.x = u2.x; v2.y = u3.x;
        float2 v3; v3.x = u2.y; v3.y = u3.y;
        *(float2*)(ob + (size_t)(2*fp)     * HWn) = v0;
        *(float2*)(ob + (size_t)(2*fp + 1) * HWn) = v1;
        *(float2*)(ob + (size_t)(2*fp + 2) * HWn) = v2;
        *(float2*)(ob + (size_t)(2*fp + 3) * HWn) = v3;
    }
}

// ---------------- launch ----------------
extern "C" void kernel_launch(void* const* d_in, const int* in_sizes, int n_in,
                              void* d_out, int out_size) {
    const float* features = (const float*)d_in[0];
    const float* carrier  = (const float*)d_in[1];
    const float* density  = (const float*)d_in[2];
    const float* w1 = (const float*)d_in[3];
    const float* b1 = (const float*)d_in[4];
    const float* w2 = (const float*)d_in[5];
    const float* b2 = (const float*)d_in[6];
    const float* w3 = (const float*)d_in[7];
    const float* b3 = (const float*)d_in[8];
    const float* w4 = (const float*)d_in[9];
    const float* b4 = (const float*)d_in[10];
    const float* proto = (const float*)d_in[11];
    float* outp = (float*)d_out;

    k_init<<<1, 64>>>();
    k_conv1<<<288, 256>>>(features, w1, b1);
    k_conv2<<<dim3(6, 6, 8), 256>>>(w2, b2);
    k_pre<<<96, 256>>>(carrier, density);
    k_morph<<<96, 256>>>(density);
    k_sel<<<Bn, 1024>>>(proto);
    k_final<<<576, 128>>>(w3, b3, w4, b4, outp);
}

// round 10
// speedup vs baseline: 1.0054x; 1.0054x over previous
#include <cuda_runtime.h>
#include <math.h>
#include <float.h>

#define Bn    8
#define Hn    96
#define Wn    96
#define HWn   9216
#define FCn   768
#define Rn    12
#define Pn    16
#define KSn   13
#define TOPKn 24
#define SELCAP 2048

typedef unsigned long long ull;

// ---------------- scratch (device globals) ----------------
__device__ float g_t1[Bn*Rn*HWn];
__device__ float g_proj[Bn*Rn*HWn];
__device__ float g_canvas[Bn*Rn*HWn];
__device__ float g_occraw[Bn*HWn];
__device__ float g_cavg[Bn*HWn];
__device__ float g_sup[Bn*HWn];
__device__ float g_occ[Bn*HWn];
__device__ float g_dnorm[Bn*HWn];
__device__ float g_anch[Bn*HWn];
__device__ unsigned g_umn[24], g_umx[24];   // [0..7] occraw, [8..15] density, [16..23] cavg
__device__ int   g_ncand[Bn];
__device__ int   g_done[Bn];
__device__ float g_cand_v[Bn*HWn];
__device__ int   g_cand_i[Bn*HWn];

// ---------------- helpers ----------------
__device__ __forceinline__ void ffma2(ull &acc, ull a, ull b) {
    asm("fma.rn.f32x2 %0, %1, %2, %0;" : "+l"(acc) : "l"(a), "l"(b));
}
__device__ __forceinline__ ull dup2(float x) {
    ull r;
    asm("mov.b64 %0, {%1, %1};" : "=l"(r) : "f"(x));
    return r;
}
__device__ __forceinline__ float2 unpack2(ull v) {
    float2 r;
    asm("mov.b64 {%0, %1}, %2;" : "=f"(r.x), "=f"(r.y) : "l"(v));
    return r;
}
__device__ __forceinline__ float gelu_exact(float x) {
    return 0.5f * x * (1.0f + erff(x * 0.70710678118654752440f));
}

// padded-tile stencils: storage col of global x is x+1, row stride 100
__device__ __forceinline__ float pmax3(const float* S, int cr, int x) {
    const float* p = S + (cr - 1) * 100 + x;
    float a = fmaxf(fmaxf(p[0],   p[1]),   p[2]);
    float b = fmaxf(fmaxf(p[100], p[101]), p[102]);
    float c = fmaxf(fmaxf(p[200], p[201]), p[202]);
    return fmaxf(a, fmaxf(b, c));
}
__device__ __forceinline__ float pmin3(const float* S, int cr, int x) {
    const float* p = S + (cr - 1) * 100 + x;
    float a = fminf(fminf(p[0],   p[1]),   p[2]);
    float b = fminf(fminf(p[100], p[101]), p[102]);
    float c = fminf(fminf(p[200], p[201]), p[202]);
    return fminf(a, fminf(b, c));
}

// ---------------- K1: conv1x1 FC->R + gelu (3-buffer deep LDG pipeline) ----------------
__global__ void __launch_bounds__(256, 2) k_conv1(const float* __restrict__ feat,
                                                  const float* __restrict__ w1,
                                                  const float* __restrict__ b1) {
    if (blockIdx.x == 0) {       // reset stats/counters for later stages
        int t = threadIdx.x;
        if (t < 24) { g_umn[t] = 0x7f800000u; g_umx[t] = 0u; }
        else if (t < 32) { g_ncand[t - 24] = 0; g_done[t - 24] = 0; }
    }
    __shared__ __align__(16) float sw[FCn*Rn];
    for (int i = threadIdx.x; i < FCn*Rn; i += 256) {
        int c = i / Rn, r = i - c*Rn;
        sw[i] = w1[r*FCn + c];
    }
    __syncthreads();
    int b = blockIdx.x / 36;
    int p = (blockIdx.x % 36) * 256 + threadIdx.x;
    const float* fb = feat + (size_t)b * FCn * HWn + p;

    ull acc[6];
#pragma unroll
    for (int j = 0; j < 6; j++) acc[j] = 0ull;

    const ulonglong2* wv = (const ulonglong2*)sw;

#define LOAD8(X, CH) do { \
    _Pragma("unroll") \
    for (int u_ = 0; u_ < 8; u_++) X[u_] = fb[(size_t)((CH) + u_) * HWn]; \
} while (0)
#define COMP8(X, CH) do { \
    _Pragma("unroll") \
    for (int u_ = 0; u_ < 8; u_++) { \
        ull d_ = dup2(X[u_]); \
        const ulonglong2* w_ = wv + ((CH) + u_) * 3; \
        ulonglong2 q0 = w_[0], q1 = w_[1], q2 = w_[2]; \
        ffma2(acc[0], d_, q0.x); ffma2(acc[1], d_, q0.y); \
        ffma2(acc[2], d_, q1.x); ffma2(acc[3], d_, q1.y); \
        ffma2(acc[4], d_, q2.x); ffma2(acc[5], d_, q2.y); \
    } \
} while (0)

    float A[8], B[8], C[8];
    LOAD8(A, 0); LOAD8(B, 8); LOAD8(C, 16);
    int cb = 0;
#pragma unroll 1
    for (int it = 0; it < 31; it++) {
        COMP8(A, cb);      LOAD8(A, cb + 24);
        COMP8(B, cb + 8);  LOAD8(B, cb + 32);
        COMP8(C, cb + 16); LOAD8(C, cb + 40);
        cb += 24;
    }
    COMP8(A, 744); COMP8(B, 752); COMP8(C, 760);
#undef LOAD8
#undef COMP8

    float* op = g_t1 + (size_t)b * Rn * HWn + p;
#pragma unroll
    for (int j = 0; j < 6; j++) {
        float2 a = unpack2(acc[j]);
        op[(size_t)(2*j)     * HWn] = gelu_exact(a.x + __ldg(b1 + 2*j));
        op[(size_t)(2*j + 1) * HWn] = gelu_exact(a.y + __ldg(b1 + 2*j + 1));
    }
}

// ---------------- K2: conv3x3 + gelu + occ_raw + canvas zero + cavg + stats ----------------
__global__ void __launch_bounds__(256) k_conv2(const float* __restrict__ w2,
                                               const float* __restrict__ b2,
                                               const float* __restrict__ carrier,
                                               const float* __restrict__ density) {
    __shared__ float tile[Rn][18*18];
    __shared__ __align__(16) float sw2[Rn*Rn*9];
    __shared__ __align__(16) float sb2[Rn];
    __shared__ float red[8*6];
    int b   = blockIdx.z;
    int ty0 = blockIdx.y * 16, tx0 = blockIdx.x * 16;
    int tid = threadIdx.x, lane = tid & 31, warp = tid >> 5;
    for (int i = tid; i < Rn*Rn*9; i += 256) {
        int rout = i % 12;
        int rest = i / 12;
        int rin  = rest / 9;
        int k9   = rest % 9;
        sw2[i] = w2[(rout*12 + rin) * 9 + k9];
    }
    if (tid < Rn) sb2[tid] = b2[tid];
    const float* tin = g_t1 + (size_t)b * Rn * HWn;
    for (int i = tid; i < Rn*324; i += 256) {
        int ch = i / 324, rem = i - ch*324;
        int yy = rem / 18, xx = rem % 18;
        int gy = ty0 + yy - 1, gx = tx0 + xx - 1;
        float v = 0.0f;
        if (gy >= 0 && gy < Hn && gx >= 0 && gx < Wn)
            v = tin[(size_t)ch * HWn + gy*Wn + gx];
        tile[ch][rem] = v;
    }
    __syncthreads();
    int ty = tid / 16, tx = tid % 16;
    ull acc[6];
    {
        const ull* bb = (const ull*)sb2;
#pragma unroll
        for (int j = 0; j < 6; j++) acc[j] = bb[j];
    }
    const ulonglong2* wv = (const ulonglong2*)sw2;
#pragma unroll
    for (int rin = 0; rin < 12; rin++) {
#pragma unroll
        for (int k9 = 0; k9 < 9; k9++) {
            int ky = k9 / 3, kx = k9 % 3;
            ull d = dup2(tile[rin][(ty + ky)*18 + tx + kx]);
            const ulonglong2* w = wv + (rin*9 + k9) * 3;
            ulonglong2 w0 = w[0], w1v = w[1], w2v = w[2];
            ffma2(acc[0], d, w0.x);  ffma2(acc[1], d, w0.y);
            ffma2(acc[2], d, w1v.x); ffma2(acc[3], d, w1v.y);
            ffma2(acc[4], d, w2v.x); ffma2(acc[5], d, w2v.y);
        }
    }
    int p = (ty0 + ty)*Wn + tx0 + tx;
    float* pout = g_proj + (size_t)b * Rn * HWn + p;
    float* cz   = g_canvas + (size_t)b * Rn * HWn + p;
    float asum = 0.0f;
#pragma unroll
    for (int j = 0; j < 6; j++) {
        float2 a = unpack2(acc[j]);
        float g0 = gelu_exact(a.x), g1 = gelu_exact(a.y);
        pout[(size_t)(2*j)     * HWn] = g0;
        pout[(size_t)(2*j + 1) * HWn] = g1;
        cz[(size_t)(2*j)     * HWn] = 0.0f;
        cz[(size_t)(2*j + 1) * HWn] = 0.0f;
        asum += fabsf(g0) + fabsf(g1);
    }
    float ov = asum * (1.0f / 12.0f);
    g_occraw[b*HWn + p] = ov;

    // ---- cavg (|carrier| halo tile, reusing tile[0]) + per-batch stats ----
    __syncthreads();
    float* car = &tile[0][0];
    const float* cb2 = carrier + (size_t)b * HWn;
    for (int i = tid; i < 324; i += 256) {
        int yy = i / 18, xx = i - yy*18;
        int gy = ty0 + yy - 1, gx = tx0 + xx - 1;
        float v = 0.0f;
        if (gy >= 0 && gy < Hn && gx >= 0 && gx < Wn)
            v = fabsf(cb2[gy*Wn + gx]);
        car[i] = v;
    }
    __syncthreads();
    float cv = 0.0f;
#pragma unroll
    for (int d = 0; d < 3; d++)
        cv += car[(ty+d)*18 + tx] + car[(ty+d)*18 + tx + 1] + car[(ty+d)*18 + tx + 2];
    cv *= (1.0f / 9.0f);
    g_cavg[b*HWn + p] = cv;
    float dv = density[(size_t)b*HWn + p];

    float mn0 = ov, mx0 = ov, mn1 = dv, mx1 = dv, mn2 = cv, mx2 = cv;
#pragma unroll
    for (int off = 16; off; off >>= 1) {
        mn0 = fminf(mn0, __shfl_xor_sync(0xffffffffu, mn0, off));
        mx0 = fmaxf(mx0, __shfl_xor_sync(0xffffffffu, mx0, off));
        mn1 = fminf(mn1, __shfl_xor_sync(0xffffffffu, mn1, off));
        mx1 = fmaxf(mx1, __shfl_xor_sync(0xffffffffu, mx1, off));
        mn2 = fminf(mn2, __shfl_xor_sync(0xffffffffu, mn2, off));
        mx2 = fmaxf(mx2, __shfl_xor_sync(0xffffffffu, mx2, off));
    }
    if (!lane) {
        red[warp*6 + 0] = mn0; red[warp*6 + 1] = mx0;
        red[warp*6 + 2] = mn1; red[warp*6 + 3] = mx1;
        red[warp*6 + 4] = mn2; red[warp*6 + 5] = mx2;
    }
    __syncthreads();
    if (tid < 6) {
        float r = red[tid];
        bool ismax = (tid & 1);
        for (int wgt = 1; wgt < 8; wgt++) {
            float v = red[wgt*6 + tid];
            r = ismax ? fmaxf(r, v) : fminf(r, v);
        }
        int q = tid >> 1;       // 0=occraw 1=density 2=cavg
        if (ismax) atomicMax(&g_umx[q*8 + b], __float_as_uint(r));
        else       atomicMin(&g_umn[q*8 + b], __float_as_uint(r));
    }
}

// ---------------- K_morph: morphology + NMS + compaction + (last block) top-k/stamp ----------------
__device__ __constant__ float c_lenL[4] = {0.4f, 0.7f, 1.0f, 1.25f};
__device__ __constant__ float c_widL[4] = {0.12f, 0.18f, 0.24f, 0.3f};

__global__ void __launch_bounds__(256) k_morph(const float* __restrict__ density,
                                               const float* __restrict__ proto) {
    __shared__ float A[16*100];
    __shared__ float Bf[16*100];
    __shared__ float scv[SELCAP];
    __shared__ int   sci[SELCAP];
    __shared__ float sprot[Pn*Rn];
    __shared__ float s_val[TOPKn];
    __shared__ int   s_idx[TOPKn];
    __shared__ int   spidx[TOPKn];
    __shared__ int   s_ticket;

    int blk = blockIdx.x;
    int b   = blk / 12;
    int r0  = (blk % 12) * 8;
    const size_t base = (size_t)b * HWn;
    int tid = threadIdx.x, lane = tid & 31;

    float omn = __uint_as_float(g_umn[b]),      omx = __uint_as_float(g_umx[b]);
    float dmn = __uint_as_float(g_umn[8 + b]),  dmx = __uint_as_float(g_umx[8 + b]);
    float cmn = __uint_as_float(g_umn[16 + b]), cmx = __uint_as_float(g_umx[16 + b]);
    float oinv = 1.0f / fmaxf(omx - omn, 1e-6f);
    float dinv = 1.0f / fmaxf(dmx - dmn, 1e-6f);
    float cinv = 1.0f / fmaxf(cmx - cmn, 1e-6f);

    // P_mask -> A (identity +inf for erode)
    for (int i = tid; i < 16*96; i += 256) {
        int cr = i / 96, x = i - cr*96;
        int gr = r0 - 4 + cr;
        float v = FLT_MAX;
        if (gr >= 0 && gr < Hn) {
            float cs = (g_cavg[base + gr*Wn + x] - cmn) * cinv;
            float dn = (density[base + gr*Wn + x] - dmn) * dinv;
            float ev = 0.8f * cs + 0.2f * dn;
            v = (ev >= 0.28f) ? 1.0f : 0.0f;
        }
        A[cr*100 + 1 + x] = v;
    }
    if (tid < 32) A[(tid >> 1)*100 + ((tid & 1) ? 97 : 0)] = FLT_MAX;
    __syncthreads();

    // P_erode -> Bf
    for (int i = tid; i < 16*96; i += 256) {
        int cr = i / 96, x = i - cr*96;
        int gr = r0 - 4 + cr;
        float v = 0.0f;
        if (cr >= 1 && cr < 15 && gr >= 0 && gr < Hn)
            v = pmin3(A, cr, x);
        Bf[cr*100 + 1 + x] = v;
    }
    if (tid < 32) Bf[(tid >> 1)*100 + ((tid & 1) ? 97 : 0)] = 0.0f;
    __syncthreads();

    // P_open -> A
    for (int i = tid; i < 16*96; i += 256) {
        int cr = i / 96, x = i - cr*96;
        int gr = r0 - 4 + cr;
        float v = 0.0f;
        if (cr >= 2 && cr < 14 && gr >= 0 && gr < Hn)
            v = fminf(fmaxf(pmax3(Bf, cr, x), 0.0f), 1.0f);
        A[cr*100 + 1 + x] = v;
    }
    if (tid < 32) A[(tid >> 1)*100 + ((tid & 1) ? 97 : 0)] = 0.0f;
    __syncthreads();

    // P_sup + scores -> Bf ; write sup/occ/dnorm/anch for own rows
    for (int i = tid; i < 16*96; i += 256) {
        int cr = i / 96, x = i - cr*96;
        int gr = r0 - 4 + cr;
        float v = 0.0f;
        if (cr >= 3 && cr < 13 && gr >= 0 && gr < Hn) {
            float sp = fminf(fmaxf(pmax3(A, cr, x), 0.0f), 1.0f);
            float oc = (g_occraw[base + gr*Wn + x] - omn) * oinv;
            v = oc * sp;
            if (cr >= 4 && cr < 12) {
                g_sup[base + gr*Wn + x] = sp;
                g_occ[base + gr*Wn + x] = oc;
                g_dnorm[base + gr*Wn + x] = (density[base + gr*Wn + x] - dmn) * dinv;
                g_anch[base + gr*Wn + x] = 0.0f;
            }
        }
        Bf[cr*100 + 1 + x] = v;
    }
    if (tid < 32) Bf[(tid >> 1)*100 + ((tid & 1) ? 97 : 0)] = 0.0f;
    __syncthreads();

    // P_nms over own rows + candidate compaction
    for (int i = tid; i < 8*96; i += 256) {
        int rr = i / 96, x = i - rr*96;
        int cr = 4 + rr;
        float sc = Bf[cr*100 + 1 + x];
        float lm = pmax3(Bf, cr, x);
        bool peak = (sc >= lm) && (sc > 0.05f);
        unsigned bal = __ballot_sync(0xffffffffu, peak);
        if (bal) {
            int leader = __ffs((int)bal) - 1;
            int cnt  = __popc(bal);
            int pref = __popc(bal & ((1u << lane) - 1u));
            int basePos = 0;
            if (lane == leader) basePos = atomicAdd(&g_ncand[b], cnt);
            basePos = __shfl_sync(0xffffffffu, basePos, leader);
            if (peak) {
                int pos = basePos + pref;
                g_cand_v[b*HWn + pos] = sc;
                g_cand_i[b*HWn + pos] = (r0 + rr)*Wn + x;
            }
        }
    }

    // ---- last-block-done: selection + proto argmax + stamping ----
    __threadfence();
    __syncthreads();
    if (tid == 0) s_ticket = atomicAdd(&g_done[b], 1);
    __syncthreads();
    if (s_ticket != 11) return;
    __threadfence();

    int nc = g_ncand[b];
    bool smem_path = (nc <= SELCAP);
    if (smem_path) {
        for (int i = tid; i < nc; i += 256) {
            scv[i] = g_cand_v[b*HWn + i];
            sci[i] = g_cand_i[b*HWn + i];
        }
    }
    if (tid < Pn*Rn) sprot[tid] = proto[tid];
    __syncthreads();

    if (tid < 32) {
        float* cvv = smem_path ? scv : (g_cand_v + b*HWn);
        int*   cii = smem_path ? sci : (g_cand_i + b*HWn);
        for (int k = 0; k < TOPKn; k++) {
            float v = -FLT_MAX; int bi = 0x7fffffff; int bp = -1;
            for (int p = lane; p < nc; p += 32) {
                float m = cvv[p]; int ix = cii[p];
                if (m > v || (m == v && ix < bi)) { v = m; bi = ix; bp = p; }
            }
            float myv = v; int mybi = bi;
#pragma unroll
            for (int off = 16; off; off >>= 1) {
                float ov = __shfl_xor_sync(0xffffffffu, v, off);
                int   oi = __shfl_xor_sync(0xffffffffu, bi, off);
                if (ov > v || (ov == v && oi < bi)) { v = ov; bi = oi; }
            }
            if (v > 0.0f && myv == v && mybi == bi && bp >= 0)
                cvv[bp] = -FLT_MAX;
            if (!smem_path) __threadfence_block();
            __syncwarp();
            if (!lane) {
                if (v > 0.0f) { s_val[k] = v;    s_idx[k] = bi; }
                else          { s_val[k] = 0.0f; s_idx[k] = -1; }
            }
        }
    }
    __syncthreads();

    if (tid < TOPKn) {
        float v = s_val[tid];
        int   ix = s_idx[tid];
        if (v > 0.0f && ix >= 0) {
            g_anch[base + ix] = v;
            float f[Rn];
#pragma unroll
            for (int r = 0; r < Rn; r++)
                f[r] = g_proj[((size_t)b*Rn + r) * HWn + ix];
            float best = -FLT_MAX; int bp = 0;
#pragma unroll
            for (int p = 0; p < Pn; p++) {
                float l = 0.0f;
#pragma unroll
                for (int r = 0; r < Rn; r++) l += f[r] * sprot[p*Rn + r];
                if (l > best) { best = l; bp = p; }
            }
            spidx[tid] = bp;
        } else {
            spidx[tid] = 0;
        }
    }
    __syncthreads();

    for (int wk = tid; wk < TOPKn * KSn * KSn; wk += 256) {
        int a = wk / (KSn*KSn);
        int t = wk - a * (KSn*KSn);
        float val = s_val[a];
        if (val <= 0.0f) continue;
        int idx = s_idx[a];
        int pi  = spidx[a];
        int ys = idx / Wn, xs = idx % Wn;
        int dy = t / KSn, dx = t % KSn;
        int y = ys + dy - KSn/2, x = xs + dx - KSn/2;
        if (y < 0 || y >= Hn || x < 0 || x >= Wn) continue;
        float gx  = (float)(-1.0 + (double)dx * (2.0 / 12.0));
        float gy  = (float)(-1.0 + (double)dy * (2.0 / 12.0));
        float ori = (float)((double)pi * (3.14159265358979323846 / 16.0));
        float ln  = c_lenL[pi & 3];
        float wd  = c_widL[(pi >> 2) & 3];
        float c = cosf(ori), s = sinf(ori);
        float xr =  c * gx + s * gy;
        float yr = -s * gx + c * gy;
        float txx = xr / ln, tyy = yr / wd;
        float foot = expf(-(txx*txx) - (tyy*tyy)) * val;
        float* cvp = g_canvas + (size_t)b * Rn * HWn + y*Wn + x;
#pragma unroll
        for (int r = 0; r < Rn; r++)
            atomicAdd(cvp + (size_t)r * HWn, sprot[pi*Rn + r] * foot);
    }
}

// ---------------- final: (16->12 gelu)->(12->768), f-split x2, 4 acc chains ----------------
__global__ void __launch_bounds__(128) k_final(const float* __restrict__ w3,
                                               const float* __restrict__ b3,
                                               const float* __restrict__ w4,
                                               const float* __restrict__ b4,
                                               float* __restrict__ outp) {
    __shared__ __align__(16) ull wint[192*12];
    __shared__ ull bp4[192];
    __shared__ float sw3[Rn*16];
    __shared__ float sb3[Rn];

    int bx = blockIdx.x;
    int fh = bx & 1;
    int t2 = bx >> 1;
    int b  = t2 / 36;
    int f0 = fh * 384;
    {
        float* wf = (float*)wint;
        for (int i = threadIdx.x; i < 384*Rn; i += 128) {
            int fl = i / Rn, r = i - fl*Rn;
            wf[(fl >> 1)*24 + r*2 + (fl & 1)] = w4[(f0 + fl)*Rn + r];
        }
        float* bf = (float*)bp4;
        for (int i = threadIdx.x; i < 384; i += 128) bf[i] = b4[f0 + i];
        for (int i = threadIdx.x; i < Rn*16; i += 128) sw3[i] = w3[i];
        for (int i = threadIdx.x; i < Rn;    i += 128) sb3[i] = b3[i];
    }
    __syncthreads();

    int p0 = (t2 % 36) * 256 + threadIdx.x * 2;
    size_t bpx = (size_t)b * HWn + p0;

    float2 sup = *(const float2*)(g_sup + bpx);
    float2 occ = *(const float2*)(g_occ + bpx);
    float2 an  = *(const float2*)(g_anch + bpx);
    float2 dn  = *(const float2*)(g_dnorm + bpx);

    float in0[16], in1[16];
#pragma unroll
    for (int r = 0; r < Rn; r++) {
        float2 cv = *(const float2*)(g_canvas + ((size_t)b*Rn + r) * HWn + p0);
        in0[r] = cv.x * sup.x;
        in1[r] = cv.y * sup.y;
    }
    in0[12] = occ.x; in1[12] = occ.y;
    in0[13] = sup.x; in1[13] = sup.y;
    in0[14] = an.x;  in1[14] = an.y;
    in0[15] = dn.x;  in1[15] = dn.y;

    ull md0[Rn], md1[Rn];
#pragma unroll
    for (int r = 0; r < Rn; r++) {
        float m0 = sb3[r], m1 = sb3[r];
#pragma unroll
        for (int j = 0; j < 16; j++) {
            float w = sw3[r*16 + j];
            m0 += in0[j] * w;
            m1 += in1[j] * w;
        }
        md0[r] = dup2(gelu_exact(m0));
        md1[r] = dup2(gelu_exact(m1));
    }

    float* ob = outp + (size_t)b * FCn * HWn + (size_t)f0 * HWn + p0;
    const ulonglong2* wv = (const ulonglong2*)wint;
#pragma unroll 2
    for (int fp = 0; fp < 192; fp += 2) {
        ull a0 = bp4[fp];
        ull a1 = a0;
        ull a2 = bp4[fp + 1];
        ull a3 = a2;
        const ulonglong2* w = wv + fp*6;
#pragma unroll
        for (int q = 0; q < 6; q++) {
            ulonglong2 wq = w[q];
            ulonglong2 w2 = w[q + 6];
            ffma2(a0, md0[2*q],     wq.x);
            ffma2(a1, md1[2*q],     wq.x);
            ffma2(a2, md0[2*q],     w2.x);
            ffma2(a3, md1[2*q],     w2.x);
            ffma2(a0, md0[2*q + 1], wq.y);
            ffma2(a1, md1[2*q + 1], wq.y);
            ffma2(a2, md0[2*q + 1], w2.y);
            ffma2(a3, md1[2*q + 1], w2.y);
        }
        float2 u0 = unpack2(a0), u1 = unpack2(a1);
        float2 u2 = unpack2(a2), u3 = unpack2(a3);
        float2 v0; v0.x = u0.x; v0.y = u1.x;
        float2 v1; v1.x = u0.y; v1.y = u1.y;
        float2 v2; v2.x = u2.x; v2.y = u3.x;
        float2 v3; v3.x = u2.y; v3.y = u3.y;
        *(float2*)(ob + (size_t)(2*fp)     * HWn) = v0;
        *(float2*)(ob + (size_t)(2*fp + 1) * HWn) = v1;
        *(float2*)(ob + (size_t)(2*fp + 2) * HWn) = v2;
        *(float2*)(ob + (size_t)(2*fp + 3) * HWn) = v3;
    }
}

// ---------------- launch ----------------
extern "C" void kernel_launch(void* const* d_in, const int* in_sizes, int n_in,
                              void* d_out, int out_size) {
    const float* features = (const float*)d_in[0];
    const float* carrier  = (const float*)d_in[1];
    const float* density  = (const float*)d_in[2];
    const float* w1 = (const float*)d_in[3];
    const float* b1 = (const float*)d_in[4];
    const float* w2 = (const float*)d_in[5];
    const float* b2 = (const float*)d_in[6];
    const float* w3 = (const float*)d_in[7];
    const float* b3 = (const float*)d_in[8];
    const float* w4 = (const float*)d_in[9];
    const float* b4 = (const float*)d_in[10];
    const float* proto = (const float*)d_in[11];
    float* outp = (float*)d_out;

    k_conv1<<<288, 256>>>(features, w1, b1);
    k_conv2<<<dim3(6, 6, 8), 256>>>(w2, b2, carrier, density);
    k_morph<<<96, 256>>>(density, proto);
    k_final<<<576, 128>>>(w3, b3, w4, b4, outp);
}

// round 11
// speedup vs baseline: 1.0271x; 1.0216x over previous
#include <cuda_runtime.h>
#include <math.h>
#include <float.h>

#define Bn    8
#define Hn    96
#define Wn    96
#define HWn   9216
#define FCn   768
#define Rn    12
#define Pn    16
#define KSn   13
#define TOPKn 24

typedef unsigned long long ull;

// ---------------- scratch (device globals) ----------------
__device__ float g_t1[Bn*Rn*HWn];
__device__ float g_proj[Bn*Rn*HWn];
__device__ float g_canvas[Bn*Rn*HWn];
__device__ float g_occraw[Bn*HWn];
__device__ float g_sup[Bn*HWn];
__device__ float g_occ[Bn*HWn];
__device__ float g_dnorm[Bn*HWn];
__device__ float g_anch[Bn*HWn];

// ---------------- helpers ----------------
__device__ __forceinline__ void ffma2(ull &acc, ull a, ull b) {
    asm("fma.rn.f32x2 %0, %1, %2, %0;" : "+l"(acc) : "l"(a), "l"(b));
}
__device__ __forceinline__ ull dup2(float x) {
    ull r;
    asm("mov.b64 %0, {%1, %1};" : "=l"(r) : "f"(x));
    return r;
}
__device__ __forceinline__ float2 unpack2(ull v) {
    float2 r;
    asm("mov.b64 {%0, %1}, %2;" : "=f"(r.x), "=f"(r.y) : "l"(v));
    return r;
}
__device__ __forceinline__ float gelu_exact(float x) {
    return 0.5f * x * (1.0f + erff(x * 0.70710678118654752440f));
}

// ---------------- K1: conv1x1 FC->R + gelu (2-buffer pipeline, 4 CTA/SM) ----------------
__global__ void __launch_bounds__(256, 4) k_conv1(const float* __restrict__ feat,
                                                  const float* __restrict__ w1,
                                                  const float* __restrict__ b1) {
    __shared__ __align__(16) float sw[FCn*Rn];   // 36 KB; 4 CTAs -> 147.5 KB/SM
    for (int i = threadIdx.x; i < FCn*Rn; i += 256) {
        int c = i / Rn, r = i - c*Rn;
        sw[i] = w1[r*FCn + c];
    }
    __syncthreads();
    int b = blockIdx.x / 36;
    int p = (blockIdx.x % 36) * 256 + threadIdx.x;
    const float* fb = feat + (size_t)b * FCn * HWn + p;

    ull acc[6];
#pragma unroll
    for (int j = 0; j < 6; j++) acc[j] = 0ull;

    const ulonglong2* wv = (const ulonglong2*)sw;  // 3 per channel

#define LOAD8(X, CH) do { \
    _Pragma("unroll") \
    for (int u_ = 0; u_ < 8; u_++) X[u_] = fb[(size_t)((CH) + u_) * HWn]; \
} while (0)
#define COMP8(X, CH) do { \
    _Pragma("unroll") \
    for (int u_ = 0; u_ < 8; u_++) { \
        ull d_ = dup2(X[u_]); \
        const ulonglong2* w_ = wv + ((CH) + u_) * 3; \
        ulonglong2 q0 = w_[0], q1 = w_[1], q2 = w_[2]; \
        ffma2(acc[0], d_, q0.x); ffma2(acc[1], d_, q0.y); \
        ffma2(acc[2], d_, q1.x); ffma2(acc[3], d_, q1.y); \
        ffma2(acc[4], d_, q2.x); ffma2(acc[5], d_, q2.y); \
    } \
} while (0)

    float A[8], B[8];
    LOAD8(A, 0); LOAD8(B, 8);
    int cb = 0;
#pragma unroll 1
    for (int it = 0; it < 47; it++) {     // 47*16 = 752 channels in loop
        COMP8(A, cb);      LOAD8(A, cb + 16);
        COMP8(B, cb + 8);  LOAD8(B, cb + 24);
        cb += 16;
    }
    // cb == 752: A = 752..759, B = 760..767 already loaded
    COMP8(A, 752); COMP8(B, 760);
#undef LOAD8
#undef COMP8

    float* op = g_t1 + (size_t)b * Rn * HWn + p;
#pragma unroll
    for (int j = 0; j < 6; j++) {
        float2 a = unpack2(acc[j]);
        op[(size_t)(2*j)     * HWn] = gelu_exact(a.x + __ldg(b1 + 2*j));
        op[(size_t)(2*j + 1) * HWn] = gelu_exact(a.y + __ldg(b1 + 2*j + 1));
    }
}

// ---------------- K2: conv3x3 R->R + gelu + occ_raw + canvas zero ----------------
__global__ void __launch_bounds__(256) k_conv2(const float* __restrict__ w2,
                                               const float* __restrict__ b2) {
    __shared__ float tile[Rn][18*18];
    __shared__ __align__(16) float sw2[Rn*Rn*9];
    __shared__ __align__(16) float sb2[Rn];
    int b   = blockIdx.z;
    int ty0 = blockIdx.y * 16, tx0 = blockIdx.x * 16;
    for (int i = threadIdx.x; i < Rn*Rn*9; i += 256) {
        int rout = i % 12;
        int rest = i / 12;
        int rin  = rest / 9;
        int k9   = rest % 9;
        sw2[i] = w2[(rout*12 + rin) * 9 + k9];
    }
    if (threadIdx.x < Rn) sb2[threadIdx.x] = b2[threadIdx.x];
    const float* tin = g_t1 + (size_t)b * Rn * HWn;
    for (int i = threadIdx.x; i < Rn*324; i += 256) {
        int ch = i / 324, rem = i - ch*324;
        int yy = rem / 18, xx = rem % 18;
        int gy = ty0 + yy - 1, gx = tx0 + xx - 1;
        float v = 0.0f;
        if (gy >= 0 && gy < Hn && gx >= 0 && gx < Wn)
            v = tin[(size_t)ch * HWn + gy*Wn + gx];
        tile[ch][rem] = v;
    }
    __syncthreads();
    int ty = threadIdx.x / 16, tx = threadIdx.x % 16;
    ull acc[6];
    {
        const ull* bb = (const ull*)sb2;
#pragma unroll
        for (int j = 0; j < 6; j++) acc[j] = bb[j];
    }
    const ulonglong2* wv = (const ulonglong2*)sw2;
#pragma unroll
    for (int rin = 0; rin < 12; rin++) {
#pragma unroll
        for (int k9 = 0; k9 < 9; k9++) {
            int ky = k9 / 3, kx = k9 % 3;
            ull d = dup2(tile[rin][(ty + ky)*18 + tx + kx]);
            const ulonglong2* w = wv + (rin*9 + k9) * 3;
            ulonglong2 w0 = w[0], w1v = w[1], w2v = w[2];
            ffma2(acc[0], d, w0.x);  ffma2(acc[1], d, w0.y);
            ffma2(acc[2], d, w1v.x); ffma2(acc[3], d, w1v.y);
            ffma2(acc[4], d, w2v.x); ffma2(acc[5], d, w2v.y);
        }
    }
    int p = (ty0 + ty)*Wn + tx0 + tx;
    float* pout = g_proj + (size_t)b * Rn * HWn + p;
    float* cz   = g_canvas + (size_t)b * Rn * HWn + p;
    float asum = 0.0f;
#pragma unroll
    for (int j = 0; j < 6; j++) {
        float2 a = unpack2(acc[j]);
        float g0 = gelu_exact(a.x), g1 = gelu_exact(a.y);
        pout[(size_t)(2*j)     * HWn] = g0;
        pout[(size_t)(2*j + 1) * HWn] = g1;
        cz[(size_t)(2*j)     * HWn] = 0.0f;
        cz[(size_t)(2*j + 1) * HWn] = 0.0f;
        asum += fabsf(g0) + fabsf(g1);
    }
    g_occraw[b*HWn + p] = asum * (1.0f / 12.0f);
}

// ---------------- fused support/NMS/top-k/proto/stamp (1 block per batch) ----------------
__device__ __forceinline__ float win3max_s(const float* S, int y, int x) {
    float r = -FLT_MAX;
#pragma unroll
    for (int dy = -1; dy <= 1; dy++) {
        int yy = y + dy; if (yy < 0 || yy >= Hn) continue;
#pragma unroll
        for (int dx = -1; dx <= 1; dx++) {
            int xx = x + dx; if (xx < 0 || xx >= Wn) continue;
            r = fmaxf(r, S[yy*Wn + xx]);
        }
    }
    return r;
}
__device__ __forceinline__ float win3min_s(const float* S, int y, int x) {
    float r = FLT_MAX;
#pragma unroll
    for (int dy = -1; dy <= 1; dy++) {
        int yy = y + dy; if (yy < 0 || yy >= Hn) continue;
#pragma unroll
        for (int dx = -1; dx <= 1; dx++) {
            int xx = x + dx; if (xx < 0 || xx >= Wn) continue;
            r = fminf(r, S[yy*Wn + xx]);
        }
    }
    return r;
}
__device__ __forceinline__ float win3sum_s(const float* S, int y, int x) {
    float r = 0.0f;
#pragma unroll
    for (int dy = -1; dy <= 1; dy++) {
        int yy = y + dy; if (yy < 0 || yy >= Hn) continue;
#pragma unroll
        for (int dx = -1; dx <= 1; dx++) {
            int xx = x + dx; if (xx < 0 || xx >= Wn) continue;
            r += S[yy*Wn + xx];
        }
    }
    return r;
}

__device__ __constant__ float c_lenL[4] = {0.4f, 0.7f, 1.0f, 1.25f};
__device__ __constant__ float c_widL[4] = {0.12f, 0.18f, 0.24f, 0.3f};

__global__ void __launch_bounds__(1024) k_fused(const float* __restrict__ carrier,
                                                const float* __restrict__ density,
                                                const float* __restrict__ proto) {
    __shared__ float S[HWn];
    __shared__ float smn[32], smx[32];
    __shared__ float rv[32];
    __shared__ int   ri[32];
    __shared__ float sprot[Pn*Rn];
    __shared__ float s_val[TOPKn];
    __shared__ int   s_idx[TOPKn];
    __shared__ int   spidx[TOPKn];
    __shared__ int   s_bi;

    int b = blockIdx.x, tid = threadIdx.x;
    int lane = tid & 31, warp = tid >> 5;
    const size_t base = (size_t)b * HWn;

    if (tid < Pn*Rn) sprot[tid] = proto[tid];

    float dreg[9], oreg[9];
    float dmn = FLT_MAX, dmx = -FLT_MAX, omn = FLT_MAX, omx = -FLT_MAX;
#pragma unroll
    for (int j = 0; j < 9; j++) {
        int px = tid + j*1024;
        float d = density[base + px];
        float o = g_occraw[base + px];
        dreg[j] = d; oreg[j] = o;
        dmn = fminf(dmn, d); dmx = fmaxf(dmx, d);
        omn = fminf(omn, o); omx = fmaxf(omx, o);
        S[px] = fabsf(carrier[base + px]);
    }
#pragma unroll
    for (int off = 16; off; off >>= 1) {
        dmn = fminf(dmn, __shfl_down_sync(0xffffffffu, dmn, off));
        dmx = fmaxf(dmx, __shfl_down_sync(0xffffffffu, dmx, off));
        omn = fminf(omn, __shfl_down_sync(0xffffffffu, omn, off));
        omx = fmaxf(omx, __shfl_down_sync(0xffffffffu, omx, off));
    }
    if (!lane) { smn[warp] = dmn; smx[warp] = dmx; rv[warp] = omn; ri[warp] = __float_as_int(omx); }
    __syncthreads();
    if (tid < 32) {
        float a = smn[lane], c = smx[lane], e = rv[lane], f = __int_as_float(ri[lane]);
#pragma unroll
        for (int off = 16; off; off >>= 1) {
            a = fminf(a, __shfl_down_sync(0xffffffffu, a, off));
            c = fmaxf(c, __shfl_down_sync(0xffffffffu, c, off));
            e = fminf(e, __shfl_down_sync(0xffffffffu, e, off));
            f = fmaxf(f, __shfl_down_sync(0xffffffffu, f, off));
        }
        if (!lane) { smn[0] = a; smx[0] = c; rv[0] = e; ri[0] = __float_as_int(f); }
    }
    __syncthreads();
    dmn = smn[0]; dmx = smx[0]; omn = rv[0]; omx = __int_as_float(ri[0]);
    __syncthreads();

    float cav[9];
    float cmn = FLT_MAX, cmx = -FLT_MAX;
#pragma unroll
    for (int j = 0; j < 9; j++) {
        int px = tid + j*1024;
        int y = px / Wn, x = px - y*Wn;
        float v = win3sum_s(S, y, x) * (1.0f / 9.0f);
        cav[j] = v;
        cmn = fminf(cmn, v); cmx = fmaxf(cmx, v);
    }
#pragma unroll
    for (int off = 16; off; off >>= 1) {
        cmn = fminf(cmn, __shfl_down_sync(0xffffffffu, cmn, off));
        cmx = fmaxf(cmx, __shfl_down_sync(0xffffffffu, cmx, off));
    }
    if (!lane) { smn[warp] = cmn; smx[warp] = cmx; }
    __syncthreads();
    if (tid < 32) {
        float a = smn[lane], c = smx[lane];
#pragma unroll
        for (int off = 16; off; off >>= 1) {
            a = fminf(a, __shfl_down_sync(0xffffffffu, a, off));
            c = fmaxf(c, __shfl_down_sync(0xffffffffu, c, off));
        }
        if (!lane) { smn[0] = a; smx[0] = c; }
    }
    __syncthreads();
    cmn = smn[0]; cmx = smx[0];

    float dinv = 1.0f / fmaxf(dmx - dmn, 1e-6f);
    float oinv = 1.0f / fmaxf(omx - omn, 1e-6f);
    float cinv = 1.0f / fmaxf(cmx - cmn, 1e-6f);

    float occ[9], mval[9];
#pragma unroll
    for (int j = 0; j < 9; j++) {
        int px = tid + j*1024;
        float dn = (dreg[j] - dmn) * dinv;
        float oc = (oreg[j] - omn) * oinv;
        float cs = (cav[j] - cmn) * cinv;
        g_dnorm[base + px] = dn;
        g_occ[base + px] = oc;
        occ[j] = oc;
        float ev = 0.8f * cs + 0.2f * dn;
        mval[j] = (ev >= 0.28f) ? 1.0f : 0.0f;
    }
    __syncthreads();
#pragma unroll
    for (int j = 0; j < 9; j++) S[tid + j*1024] = mval[j];
    __syncthreads();
    float er[9];
#pragma unroll
    for (int j = 0; j < 9; j++) {
        int px = tid + j*1024;
        er[j] = win3min_s(S, px / Wn, px % Wn);
    }
    __syncthreads();
#pragma unroll
    for (int j = 0; j < 9; j++) S[tid + j*1024] = er[j];
    __syncthreads();
    float op[9];
#pragma unroll
    for (int j = 0; j < 9; j++) {
        int px = tid + j*1024;
        op[j] = fminf(fmaxf(win3max_s(S, px / Wn, px % Wn), 0.0f), 1.0f);
    }
    __syncthreads();
#pragma unroll
    for (int j = 0; j < 9; j++) S[tid + j*1024] = op[j];
    __syncthreads();
    float sc[9];
#pragma unroll
    for (int j = 0; j < 9; j++) {
        int px = tid + j*1024;
        float sp = fminf(fmaxf(win3max_s(S, px / Wn, px % Wn), 0.0f), 1.0f);
        g_sup[base + px] = sp;
        sc[j] = occ[j] * sp;
    }
    __syncthreads();
#pragma unroll
    for (int j = 0; j < 9; j++) S[tid + j*1024] = sc[j];
    __syncthreads();
    float masked[9];
#pragma unroll
    for (int j = 0; j < 9; j++) {
        int px = tid + j*1024;
        float lm = win3max_s(S, px / Wn, px % Wn);
        masked[j] = (sc[j] >= lm && sc[j] > 0.05f) ? sc[j] : 0.0f;
        g_anch[base + px] = 0.0f;
    }
    __syncthreads();

    for (int k = 0; k < TOPKn; k++) {
        float v = -FLT_MAX; int bi = 0x7fffffff;
#pragma unroll
        for (int j = 0; j < 9; j++) {
            float m = masked[j]; int ix = tid + j*1024;
            if (m > v || (m == v && ix < bi)) { v = m; bi = ix; }
        }
#pragma unroll
        for (int off = 16; off; off >>= 1) {
            float ov = __shfl_down_sync(0xffffffffu, v, off);
            int   oi = __shfl_down_sync(0xffffffffu, bi, off);
            if (ov > v || (ov == v && oi < bi)) { v = ov; bi = oi; }
        }
        if (!lane) { rv[warp] = v; ri[warp] = bi; }
        __syncthreads();
        if (tid < 32) {
            v = rv[lane]; bi = ri[lane];
#pragma unroll
            for (int off = 16; off; off >>= 1) {
                float ov = __shfl_down_sync(0xffffffffu, v, off);
                int   oi = __shfl_down_sync(0xffffffffu, bi, off);
                if (ov > v || (ov == v && oi < bi)) { v = ov; bi = oi; }
            }
            if (!lane) { s_val[k] = v; s_idx[k] = bi; s_bi = bi; }
        }
        __syncthreads();
        int win = s_bi;
        if ((win & 1023) == tid) masked[win >> 10] = -FLT_MAX;
    }
    __syncthreads();

    if (tid < TOPKn) {
        float v = s_val[tid];
        int   ix = s_idx[tid];
        g_anch[base + ix] = v;
        float f[Rn];
#pragma unroll
        for (int r = 0; r < Rn; r++)
            f[r] = g_proj[((size_t)b*Rn + r) * HWn + ix];
        float best = -FLT_MAX; int bp = 0;
#pragma unroll
        for (int p = 0; p < Pn; p++) {
            float l = 0.0f;
#pragma unroll
            for (int r = 0; r < Rn; r++) l += f[r] * sprot[p*Rn + r];
            if (l > best) { best = l; bp = p; }
        }
        spidx[tid] = bp;
    }
    __syncthreads();

    for (int wk = tid; wk < TOPKn * KSn * KSn; wk += 1024) {
        int a = wk / (KSn*KSn);
        int t = wk - a * (KSn*KSn);
        float val = s_val[a];
        if (val <= 0.0f) continue;
        int idx = s_idx[a];
        int pi  = spidx[a];
        int ys = idx / Wn, xs = idx % Wn;
        int dy = t / KSn, dx = t % KSn;
        int y = ys + dy - KSn/2, x = xs + dx - KSn/2;
        if (y < 0 || y >= Hn || x < 0 || x >= Wn) continue;
        float gx  = (float)(-1.0 + (double)dx * (2.0 / 12.0));
        float gy  = (float)(-1.0 + (double)dy * (2.0 / 12.0));
        float ori = (float)((double)pi * (3.14159265358979323846 / 16.0));
        float ln  = c_lenL[pi & 3];
        float wd  = c_widL[(pi >> 2) & 3];
        float c = cosf(ori), s = sinf(ori);
        float xr =  c * gx + s * gy;
        float yr = -s * gx + c * gy;
        float txx = xr / ln, tyy = yr / wd;
        float foot = expf(-(txx*txx) - (tyy*tyy)) * val;
        float* cv = g_canvas + (size_t)b * Rn * HWn + y*Wn + x;
#pragma unroll
        for (int r = 0; r < Rn; r++)
            atomicAdd(cv + (size_t)r * HWn, sprot[pi*Rn + r] * foot);
    }
}

// ---------------- final: (16->12 gelu)->(12->768), f-split x2, 4 acc chains ----------------
__global__ void __launch_bounds__(128) k_final(const float* __restrict__ w3,
                                               const float* __restrict__ b3,
                                               const float* __restrict__ w4,
                                               const float* __restrict__ b4,
                                               float* __restrict__ outp) {
    __shared__ __align__(16) ull wint[192*12];
    __shared__ ull bp4[192];
    __shared__ float sw3[Rn*16];
    __shared__ float sb3[Rn];

    int bx = blockIdx.x;
    int fh = bx & 1;
    int t2 = bx >> 1;
    int b  = t2 / 36;
    int f0 = fh * 384;
    {
        float* wf = (float*)wint;
        for (int i = threadIdx.x; i < 384*Rn; i += 128) {
            int fl = i / Rn, r = i - fl*Rn;
            wf[(fl >> 1)*24 + r*2 + (fl & 1)] = w4[(f0 + fl)*Rn + r];
        }
        float* bf = (float*)bp4;
        for (int i = threadIdx.x; i < 384; i += 128) bf[i] = b4[f0 + i];
        for (int i = threadIdx.x; i < Rn*16; i += 128) sw3[i] = w3[i];
        for (int i = threadIdx.x; i < Rn;    i += 128) sb3[i] = b3[i];
    }
    __syncthreads();

    int p0 = (t2 % 36) * 256 + threadIdx.x * 2;
    size_t bpx = (size_t)b * HWn + p0;

    float2 sup = *(const float2*)(g_sup + bpx);
    float2 occ = *(const float2*)(g_occ + bpx);
    float2 an  = *(const float2*)(g_anch + bpx);
    float2 dn  = *(const float2*)(g_dnorm + bpx);

    float in0[16], in1[16];
#pragma unroll
    for (int r = 0; r < Rn; r++) {
        float2 cv = *(const float2*)(g_canvas + ((size_t)b*Rn + r) * HWn + p0);
        in0[r] = cv.x * sup.x;
        in1[r] = cv.y * sup.y;
    }
    in0[12] = occ.x; in1[12] = occ.y;
    in0[13] = sup.x; in1[13] = sup.y;
    in0[14] = an.x;  in1[14] = an.y;
    in0[15] = dn.x;  in1[15] = dn.y;

    ull md0[Rn], md1[Rn];
#pragma unroll
    for (int r = 0; r < Rn; r++) {
        float m0 = sb3[r], m1 = sb3[r];
#pragma unroll
        for (int j = 0; j < 16; j++) {
            float w = sw3[r*16 + j];
            m0 += in0[j] * w;
            m1 += in1[j] * w;
        }
        md0[r] = dup2(gelu_exact(m0));
        md1[r] = dup2(gelu_exact(m1));
    }

    float* ob = outp + (size_t)b * FCn * HWn + (size_t)f0 * HWn + p0;
    const ulonglong2* wv = (const ulonglong2*)wint;
#pragma unroll 2
    for (int fp = 0; fp < 192; fp += 2) {
        ull a0 = bp4[fp];
        ull a1 = a0;
        ull a2 = bp4[fp + 1];
        ull a3 = a2;
        const ulonglong2* w = wv + fp*6;
#pragma unroll
        for (int q = 0; q < 6; q++) {
            ulonglong2 wq = w[q];
            ulonglong2 w2 = w[q + 6];
            ffma2(a0, md0[2*q],     wq.x);
            ffma2(a1, md1[2*q],     wq.x);
            ffma2(a2, md0[2*q],     w2.x);
            ffma2(a3, md1[2*q],     w2.x);
            ffma2(a0, md0[2*q + 1], wq.y);
            ffma2(a1, md1[2*q + 1], wq.y);
            ffma2(a2, md0[2*q + 1], w2.y);
            ffma2(a3, md1[2*q + 1], w2.y);
        }
        float2 u0 = unpack2(a0), u1 = unpack2(a1);
        float2 u2 = unpack2(a2), u3 = unpack2(a3);
        float2 v0; v0.x = u0.x; v0.y = u1.x;
        float2 v1; v1.x = u0.y; v1.y = u1.y;
        float2 v2; v2.x = u2.x; v2.y = u3.x;
        float2 v3; v3.x = u2.y; v3.y = u3.y;
        *(float2*)(ob + (size_t)(2*fp)     * HWn) = v0;
        *(float2*)(ob + (size_t)(2*fp + 1) * HWn) = v1;
        *(float2*)(ob + (size_t)(2*fp + 2) * HWn) = v2;
        *(float2*)(ob + (size_t)(2*fp + 3) * HWn) = v3;
    }
}

// ---------------- launch ----------------
extern "C" void kernel_launch(void* const* d_in, const int* in_sizes, int n_in,
                              void* d_out, int out_size) {
    const float* features = (const float*)d_in[0];
    const float* carrier  = (const float*)d_in[1];
    const float* density  = (const float*)d_in[2];
    const float* w1 = (const float*)d_in[3];
    const float* b1 = (const float*)d_in[4];
    const float* w2 = (const float*)d_in[5];
    const float* b2 = (const float*)d_in[6];
    const float* w3 = (const float*)d_in[7];
    const float* b3 = (const float*)d_in[8];
    const float* w4 = (const float*)d_in[9];
    const float* b4 = (const float*)d_in[10];
    const float* proto = (const float*)d_in[11];
    float* outp = (float*)d_out;

    k_conv1<<<288, 256>>>(features, w1, b1);
    k_conv2<<<dim3(6, 6, 8), 256>>>(w2, b2);
    k_fused<<<Bn, 1024>>>(carrier, density, proto);
    k_final<<<576, 128>>>(w3, b3, w4, b4, outp);
}

// round 12
// speedup vs baseline: 1.0654x; 1.0373x over previous
#include <cuda_runtime.h>
#include <math.h>
#include <float.h>

#define Bn    8
#define Hn    96
#define Wn    96
#define HWn   9216
#define FCn   768
#define Rn    12
#define Pn    16
#define KSn   13
#define TOPKn 24

typedef unsigned long long ull;

// ---------------- scratch (device globals) ----------------
__device__ float g_t1[Bn*Rn*HWn];
__device__ float g_proj[Bn*Rn*HWn];
__device__ float g_canvas[Bn*Rn*HWn];
__device__ float g_occraw[Bn*HWn];
__device__ float g_sup[Bn*HWn];
__device__ float g_occ[Bn*HWn];
__device__ float g_dnorm[Bn*HWn];
__device__ float g_anch[Bn*HWn];

// ---------------- helpers ----------------
__device__ __forceinline__ void ffma2(ull &acc, ull a, ull b) {
    asm("fma.rn.f32x2 %0, %1, %2, %0;" : "+l"(acc) : "l"(a), "l"(b));
}
__device__ __forceinline__ ull dup2(float x) {
    ull r;
    asm("mov.b64 %0, {%1, %1};" : "=l"(r) : "f"(x));
    return r;
}
__device__ __forceinline__ float2 unpack2(ull v) {
    float2 r;
    asm("mov.b64 {%0, %1}, %2;" : "=f"(r.x), "=f"(r.y) : "l"(v));
    return r;
}
__device__ __forceinline__ float gelu_exact(float x) {
    return 0.5f * x * (1.0f + erff(x * 0.70710678118654752440f));
}

// ---------------- K1: conv1x1 FC->R + gelu (2 px/thread, 3-buffer LDG pipeline) ----------------
// 144 blocks x 256 thr x 2 px. Each weight LDS.128 now feeds 2 pixels -> smem
// crossbar traffic halves (the identified conv1 bottleneck).
__global__ void __launch_bounds__(256) k_conv1(const float* __restrict__ feat,
                                               const float* __restrict__ w1,
                                               const float* __restrict__ b1) {
    __shared__ __align__(16) float sw[FCn*Rn];   // [c][r] contiguous 12 floats/channel
    for (int i = threadIdx.x; i < FCn*Rn; i += 256) {
        int c = i / Rn, r = i - c*Rn;
        sw[i] = w1[r*FCn + c];
    }
    __syncthreads();
    int b  = blockIdx.x / 18;
    int p0 = (blockIdx.x % 18) * 512 + threadIdx.x * 2;
    const float* fb = feat + (size_t)b * FCn * HWn + p0;

    ull acc0[6], acc1[6];
#pragma unroll
    for (int j = 0; j < 6; j++) { acc0[j] = 0ull; acc1[j] = 0ull; }

    const ulonglong2* wv = (const ulonglong2*)sw;  // 3 per channel

#define LOAD8(X, CH) do { \
    _Pragma("unroll") \
    for (int u_ = 0; u_ < 8; u_++) X[u_] = *(const float2*)(fb + (size_t)((CH) + u_) * HWn); \
} while (0)
#define COMP8(X, CH) do { \
    _Pragma("unroll") \
    for (int u_ = 0; u_ < 8; u_++) { \
        ull d0_ = dup2(X[u_].x); \
        ull d1_ = dup2(X[u_].y); \
        const ulonglong2* w_ = wv + ((CH) + u_) * 3; \
        ulonglong2 q0 = w_[0], q1 = w_[1], q2 = w_[2]; \
        ffma2(acc0[0], d0_, q0.x); ffma2(acc1[0], d1_, q0.x); \
        ffma2(acc0[1], d0_, q0.y); ffma2(acc1[1], d1_, q0.y); \
        ffma2(acc0[2], d0_, q1.x); ffma2(acc1[2], d1_, q1.x); \
        ffma2(acc0[3], d0_, q1.y); ffma2(acc1[3], d1_, q1.y); \
        ffma2(acc0[4], d0_, q2.x); ffma2(acc1[4], d1_, q2.x); \
        ffma2(acc0[5], d0_, q2.y); ffma2(acc1[5], d1_, q2.y); \
    } \
} while (0)

    float2 A[8], B[8], C[8];
    LOAD8(A, 0); LOAD8(B, 8); LOAD8(C, 16);
    int cb = 0;
#pragma unroll 1
    for (int it = 0; it < 31; it++) {
        COMP8(A, cb);      LOAD8(A, cb + 24);
        COMP8(B, cb + 8);  LOAD8(B, cb + 32);
        COMP8(C, cb + 16); LOAD8(C, cb + 40);
        cb += 24;
    }
    COMP8(A, 744); COMP8(B, 752); COMP8(C, 760);
#undef LOAD8
#undef COMP8

    float* op = g_t1 + (size_t)b * Rn * HWn + p0;
#pragma unroll
    for (int j = 0; j < 6; j++) {
        float2 a0 = unpack2(acc0[j]);   // px0: (r=2j, r=2j+1)
        float2 a1 = unpack2(acc1[j]);   // px1
        float bias0 = __ldg(b1 + 2*j), bias1 = __ldg(b1 + 2*j + 1);
        float2 s0; s0.x = gelu_exact(a0.x + bias0); s0.y = gelu_exact(a1.x + bias0);
        float2 s1; s1.x = gelu_exact(a0.y + bias1); s1.y = gelu_exact(a1.y + bias1);
        *(float2*)(op + (size_t)(2*j)     * HWn) = s0;
        *(float2*)(op + (size_t)(2*j + 1) * HWn) = s1;
    }
}

// ---------------- K2: conv3x3 R->R + gelu + occ_raw + canvas zero ----------------
__global__ void __launch_bounds__(256) k_conv2(const float* __restrict__ w2,
                                               const float* __restrict__ b2) {
    __shared__ float tile[Rn][18*18];
    __shared__ __align__(16) float sw2[Rn*Rn*9];
    __shared__ __align__(16) float sb2[Rn];
    int b   = blockIdx.z;
    int ty0 = blockIdx.y * 16, tx0 = blockIdx.x * 16;
    for (int i = threadIdx.x; i < Rn*Rn*9; i += 256) {
        int rout = i % 12;
        int rest = i / 12;
        int rin  = rest / 9;
        int k9   = rest % 9;
        sw2[i] = w2[(rout*12 + rin) * 9 + k9];
    }
    if (threadIdx.x < Rn) sb2[threadIdx.x] = b2[threadIdx.x];
    const float* tin = g_t1 + (size_t)b * Rn * HWn;
    for (int i = threadIdx.x; i < Rn*324; i += 256) {
        int ch = i / 324, rem = i - ch*324;
        int yy = rem / 18, xx = rem % 18;
        int gy = ty0 + yy - 1, gx = tx0 + xx - 1;
        float v = 0.0f;
        if (gy >= 0 && gy < Hn && gx >= 0 && gx < Wn)
            v = tin[(size_t)ch * HWn + gy*Wn + gx];
        tile[ch][rem] = v;
    }
    __syncthreads();
    int ty = threadIdx.x / 16, tx = threadIdx.x % 16;
    ull acc[6];
    {
        const ull* bb = (const ull*)sb2;
#pragma unroll
        for (int j = 0; j < 6; j++) acc[j] = bb[j];
    }
    const ulonglong2* wv = (const ulonglong2*)sw2;
#pragma unroll
    for (int rin = 0; rin < 12; rin++) {
#pragma unroll
        for (int k9 = 0; k9 < 9; k9++) {
            int ky = k9 / 3, kx = k9 % 3;
            ull d = dup2(tile[rin][(ty + ky)*18 + tx + kx]);
            const ulonglong2* w = wv + (rin*9 + k9) * 3;
            ulonglong2 w0 = w[0], w1v = w[1], w2v = w[2];
            ffma2(acc[0], d, w0.x);  ffma2(acc[1], d, w0.y);
            ffma2(acc[2], d, w1v.x); ffma2(acc[3], d, w1v.y);
            ffma2(acc[4], d, w2v.x); ffma2(acc[5], d, w2v.y);
        }
    }
    int p = (ty0 + ty)*Wn + tx0 + tx;
    float* pout = g_proj + (size_t)b * Rn * HWn + p;
    float* cz   = g_canvas + (size_t)b * Rn * HWn + p;
    float asum = 0.0f;
#pragma unroll
    for (int j = 0; j < 6; j++) {
        float2 a = unpack2(acc[j]);
        float g0 = gelu_exact(a.x), g1 = gelu_exact(a.y);
        pout[(size_t)(2*j)     * HWn] = g0;
        pout[(size_t)(2*j + 1) * HWn] = g1;
        cz[(size_t)(2*j)     * HWn] = 0.0f;
        cz[(size_t)(2*j + 1) * HWn] = 0.0f;
        asum += fabsf(g0) + fabsf(g1);
    }
    g_occraw[b*HWn + p] = asum * (1.0f / 12.0f);
}

// ---------------- fused support/NMS/top-k/proto/stamp (1 block per batch) ----------------
__device__ __forceinline__ float win3max_s(const float* S, int y, int x) {
    float r = -FLT_MAX;
#pragma unroll
    for (int dy = -1; dy <= 1; dy++) {
        int yy = y + dy; if (yy < 0 || yy >= Hn) continue;
#pragma unroll
        for (int dx = -1; dx <= 1; dx++) {
            int xx = x + dx; if (xx < 0 || xx >= Wn) continue;
            r = fmaxf(r, S[yy*Wn + xx]);
        }
    }
    return r;
}
__device__ __forceinline__ float win3min_s(const float* S, int y, int x) {
    float r = FLT_MAX;
#pragma unroll
    for (int dy = -1; dy <= 1; dy++) {
        int yy = y + dy; if (yy < 0 || yy >= Hn) continue;
#pragma unroll
        for (int dx = -1; dx <= 1; dx++) {
            int xx = x + dx; if (xx < 0 || xx >= Wn) continue;
            r = fminf(r, S[yy*Wn + xx]);
        }
    }
    return r;
}
__device__ __forceinline__ float win3sum_s(const float* S, int y, int x) {
    float r = 0.0f;
#pragma unroll
    for (int dy = -1; dy <= 1; dy++) {
        int yy = y + dy; if (yy < 0 || yy >= Hn) continue;
#pragma unroll
        for (int dx = -1; dx <= 1; dx++) {
            int xx = x + dx; if (xx < 0 || xx >= Wn) continue;
            r += S[yy*Wn + xx];
        }
    }
    return r;
}

__device__ __constant__ float c_lenL[4] = {0.4f, 0.7f, 1.0f, 1.25f};
__device__ __constant__ float c_widL[4] = {0.12f, 0.18f, 0.24f, 0.3f};

__global__ void __launch_bounds__(1024) k_fused(const float* __restrict__ carrier,
                                                const float* __restrict__ density,
                                                const float* __restrict__ proto) {
    __shared__ float S[HWn];
    __shared__ float smn[32], smx[32];
    __shared__ float rv[32];
    __shared__ int   ri[32];
    __shared__ float sprot[Pn*Rn];
    __shared__ float s_val[TOPKn];
    __shared__ int   s_idx[TOPKn];
    __shared__ int   spidx[TOPKn];
    __shared__ int   s_bi;

    int b = blockIdx.x, tid = threadIdx.x;
    int lane = tid & 31, warp = tid >> 5;
    const size_t base = (size_t)b * HWn;

    if (tid < Pn*Rn) sprot[tid] = proto[tid];

    float dreg[9], oreg[9];
    float dmn = FLT_MAX, dmx = -FLT_MAX, omn = FLT_MAX, omx = -FLT_MAX;
#pragma unroll
    for (int j = 0; j < 9; j++) {
        int px = tid + j*1024;
        float d = density[base + px];
        float o = g_occraw[base + px];
        dreg[j] = d; oreg[j] = o;
        dmn = fminf(dmn, d); dmx = fmaxf(dmx, d);
        omn = fminf(omn, o); omx = fmaxf(omx, o);
        S[px] = fabsf(carrier[base + px]);
    }
#pragma unroll
    for (int off = 16; off; off >>= 1) {
        dmn = fminf(dmn, __shfl_down_sync(0xffffffffu, dmn, off));
        dmx = fmaxf(dmx, __shfl_down_sync(0xffffffffu, dmx, off));
        omn = fminf(omn, __shfl_down_sync(0xffffffffu, omn, off));
        omx = fmaxf(omx, __shfl_down_sync(0xffffffffu, omx, off));
    }
    if (!lane) { smn[warp] = dmn; smx[warp] = dmx; rv[warp] = omn; ri[warp] = __float_as_int(omx); }
    __syncthreads();
    if (tid < 32) {
        float a = smn[lane], c = smx[lane], e = rv[lane], f = __int_as_float(ri[lane]);
#pragma unroll
        for (int off = 16; off; off >>= 1) {
            a = fminf(a, __shfl_down_sync(0xffffffffu, a, off));
            c = fmaxf(c, __shfl_down_sync(0xffffffffu, c, off));
            e = fminf(e, __shfl_down_sync(0xffffffffu, e, off));
            f = fmaxf(f, __shfl_down_sync(0xffffffffu, f, off));
        }
        if (!lane) { smn[0] = a; smx[0] = c; rv[0] = e; ri[0] = __float_as_int(f); }
    }
    __syncthreads();
    dmn = smn[0]; dmx = smx[0]; omn = rv[0]; omx = __int_as_float(ri[0]);
    __syncthreads();

    float cav[9];
    float cmn = FLT_MAX, cmx = -FLT_MAX;
#pragma unroll
    for (int j = 0; j < 9; j++) {
        int px = tid + j*1024;
        int y = px / Wn, x = px - y*Wn;
        float v = win3sum_s(S, y, x) * (1.0f / 9.0f);
        cav[j] = v;
        cmn = fminf(cmn, v); cmx = fmaxf(cmx, v);
    }
#pragma unroll
    for (int off = 16; off; off >>= 1) {
        cmn = fminf(cmn, __shfl_down_sync(0xffffffffu, cmn, off));
        cmx = fmaxf(cmx, __shfl_down_sync(0xffffffffu, cmx, off));
    }
    if (!lane) { smn[warp] = cmn; smx[warp] = cmx; }
    __syncthreads();
    if (tid < 32) {
        float a = smn[lane], c = smx[lane];
#pragma unroll
        for (int off = 16; off; off >>= 1) {
            a = fminf(a, __shfl_down_sync(0xffffffffu, a, off));
            c = fmaxf(c, __shfl_down_sync(0xffffffffu, c, off));
        }
        if (!lane) { smn[0] = a; smx[0] = c; }
    }
    __syncthreads();
    cmn = smn[0]; cmx = smx[0];

    float dinv = 1.0f / fmaxf(dmx - dmn, 1e-6f);
    float oinv = 1.0f / fmaxf(omx - omn, 1e-6f);
    float cinv = 1.0f / fmaxf(cmx - cmn, 1e-6f);

    float occ[9], mval[9];
#pragma unroll
    for (int j = 0; j < 9; j++) {
        int px = tid + j*1024;
        float dn = (dreg[j] - dmn) * dinv;
        float oc = (oreg[j] - omn) * oinv;
        float cs = (cav[j] - cmn) * cinv;
        g_dnorm[base + px] = dn;
        g_occ[base + px] = oc;
        occ[j] = oc;
        float ev = 0.8f * cs + 0.2f * dn;
        mval[j] = (ev >= 0.28f) ? 1.0f : 0.0f;
    }
    __syncthreads();
#pragma unroll
    for (int j = 0; j < 9; j++) S[tid + j*1024] = mval[j];
    __syncthreads();
    float er[9];
#pragma unroll
    for (int j = 0; j < 9; j++) {
        int px = tid + j*1024;
        er[j] = win3min_s(S, px / Wn, px % Wn);
    }
    __syncthreads();
#pragma unroll
    for (int j = 0; j < 9; j++) S[tid + j*1024] = er[j];
    __syncthreads();
    float op[9];
#pragma unroll
    for (int j = 0; j < 9; j++) {
        int px = tid + j*1024;
        op[j] = fminf(fmaxf(win3max_s(S, px / Wn, px % Wn), 0.0f), 1.0f);
    }
    __syncthreads();
#pragma unroll
    for (int j = 0; j < 9; j++) S[tid + j*1024] = op[j];
    __syncthreads();
    float sc[9];
#pragma unroll
    for (int j = 0; j < 9; j++) {
        int px = tid + j*1024;
        float sp = fminf(fmaxf(win3max_s(S, px / Wn, px % Wn), 0.0f), 1.0f);
        g_sup[base + px] = sp;
        sc[j] = occ[j] * sp;
    }
    __syncthreads();
#pragma unroll
    for (int j = 0; j < 9; j++) S[tid + j*1024] = sc[j];
    __syncthreads();
    float masked[9];
#pragma unroll
    for (int j = 0; j < 9; j++) {
        int px = tid + j*1024;
        float lm = win3max_s(S, px / Wn, px % Wn);
        masked[j] = (sc[j] >= lm && sc[j] > 0.05f) ? sc[j] : 0.0f;
        g_anch[base + px] = 0.0f;
    }
    __syncthreads();

    for (int k = 0; k < TOPKn; k++) {
        float v = -FLT_MAX; int bi = 0x7fffffff;
#pragma unroll
        for (int j = 0; j < 9; j++) {
            float m = masked[j]; int ix = tid + j*1024;
            if (m > v || (m == v && ix < bi)) { v = m; bi = ix; }
        }
#pragma unroll
        for (int off = 16; off; off >>= 1) {
            float ov = __shfl_down_sync(0xffffffffu, v, off);
            int   oi = __shfl_down_sync(0xffffffffu, bi, off);
            if (ov > v || (ov == v && oi < bi)) { v = ov; bi = oi; }
        }
        if (!lane) { rv[warp] = v; ri[warp] = bi; }
        __syncthreads();
        if (tid < 32) {
            v = rv[lane]; bi = ri[lane];
#pragma unroll
            for (int off = 16; off; off >>= 1) {
                float ov = __shfl_down_sync(0xffffffffu, v, off);
                int   oi = __shfl_down_sync(0xffffffffu, bi, off);
                if (ov > v || (ov == v && oi < bi)) { v = ov; bi = oi; }
            }
            if (!lane) { s_val[k] = v; s_idx[k] = bi; s_bi = bi; }
        }
        __syncthreads();
        int win = s_bi;
        if ((win & 1023) == tid) masked[win >> 10] = -FLT_MAX;
    }
    __syncthreads();

    if (tid < TOPKn) {
        float v = s_val[tid];
        int   ix = s_idx[tid];
        g_anch[base + ix] = v;
        float f[Rn];
#pragma unroll
        for (int r = 0; r < Rn; r++)
            f[r] = g_proj[((size_t)b*Rn + r) * HWn + ix];
        float best = -FLT_MAX; int bp = 0;
#pragma unroll
        for (int p = 0; p < Pn; p++) {
            float l = 0.0f;
#pragma unroll
            for (int r = 0; r < Rn; r++) l += f[r] * sprot[p*Rn + r];
            if (l > best) { best = l; bp = p; }
        }
        spidx[tid] = bp;
    }
    __syncthreads();

    for (int wk = tid; wk < TOPKn * KSn * KSn; wk += 1024) {
        int a = wk / (KSn*KSn);
        int t = wk - a * (KSn*KSn);
        float val = s_val[a];
        if (val <= 0.0f) continue;
        int idx = s_idx[a];
        int pi  = spidx[a];
        int ys = idx / Wn, xs = idx % Wn;
        int dy = t / KSn, dx = t % KSn;
        int y = ys + dy - KSn/2, x = xs + dx - KSn/2;
        if (y < 0 || y >= Hn || x < 0 || x >= Wn) continue;
        float gx  = (float)(-1.0 + (double)dx * (2.0 / 12.0));
        float gy  = (float)(-1.0 + (double)dy * (2.0 / 12.0));
        float ori = (float)((double)pi * (3.14159265358979323846 / 16.0));
        float ln  = c_lenL[pi & 3];
        float wd  = c_widL[(pi >> 2) & 3];
        float c = cosf(ori), s = sinf(ori);
        float xr =  c * gx + s * gy;
        float yr = -s * gx + c * gy;
        float txx = xr / ln, tyy = yr / wd;
        float foot = expf(-(txx*txx) - (tyy*tyy)) * val;
        float* cv = g_canvas + (size_t)b * Rn * HWn + y*Wn + x;
#pragma unroll
        for (int r = 0; r < Rn; r++)
            atomicAdd(cv + (size_t)r * HWn, sprot[pi*Rn + r] * foot);
    }
}

// ---------------- final: (16->12 gelu)->(12->768), f-split x2, 4 acc chains ----------------
__global__ void __launch_bounds__(128) k_final(const float* __restrict__ w3,
                                               const float* __restrict__ b3,
                                               const float* __restrict__ w4,
                                               const float* __restrict__ b4,
                                               float* __restrict__ outp) {
    __shared__ __align__(16) ull wint[192*12];
    __shared__ ull bp4[192];
    __shared__ float sw3[Rn*16];
    __shared__ float sb3[Rn];

    int bx = blockIdx.x;
    int fh = bx & 1;
    int t2 = bx >> 1;
    int b  = t2 / 36;
    int f0 = fh * 384;
    {
        float* wf = (float*)wint;
        for (int i = threadIdx.x; i < 384*Rn; i += 128) {
            int fl = i / Rn, r = i - fl*Rn;
            wf[(fl >> 1)*24 + r*2 + (fl & 1)] = w4[(f0 + fl)*Rn + r];
        }
        float* bf = (float*)bp4;
        for (int i = threadIdx.x; i < 384; i += 128) bf[i] = b4[f0 + i];
        for (int i = threadIdx.x; i < Rn*16; i += 128) sw3[i] = w3[i];
        for (int i = threadIdx.x; i < Rn;    i += 128) sb3[i] = b3[i];
    }
    __syncthreads();

    int p0 = (t2 % 36) * 256 + threadIdx.x * 2;
    size_t bpx = (size_t)b * HWn + p0;

    float2 sup = *(const float2*)(g_sup + bpx);
    float2 occ = *(const float2*)(g_occ + bpx);
    float2 an  = *(const float2*)(g_anch + bpx);
    float2 dn  = *(const float2*)(g_dnorm + bpx);

    float in0[16], in1[16];
#pragma unroll
    for (int r = 0; r < Rn; r++) {
        float2 cv = *(const float2*)(g_canvas + ((size_t)b*Rn + r) * HWn + p0);
        in0[r] = cv.x * sup.x;
        in1[r] = cv.y * sup.y;
    }
    in0[12] = occ.x; in1[12] = occ.y;
    in0[13] = sup.x; in1[13] = sup.y;
    in0[14] = an.x;  in1[14] = an.y;
    in0[15] = dn.x;  in1[15] = dn.y;

    ull md0[Rn], md1[Rn];
#pragma unroll
    for (int r = 0; r < Rn; r++) {
        float m0 = sb3[r], m1 = sb3[r];
#pragma unroll
        for (int j = 0; j < 16; j++) {
            float w = sw3[r*16 + j];
            m0 += in0[j] * w;
            m1 += in1[j] * w;
        }
        md0[r] = dup2(gelu_exact(m0));
        md1[r] = dup2(gelu_exact(m1));
    }

    float* ob = outp + (size_t)b * FCn * HWn + (size_t)f0 * HWn + p0;
    const ulonglong2* wv = (const ulonglong2*)wint;
#pragma unroll 2
    for (int fp = 0; fp < 192; fp += 2) {
        ull a0 = bp4[fp];
        ull a1 = a0;
        ull a2 = bp4[fp + 1];
        ull a3 = a2;
        const ulonglong2* w = wv + fp*6;
#pragma unroll
        for (int q = 0; q < 6; q++) {
            ulonglong2 wq = w[q];
            ulonglong2 w2 = w[q + 6];
            ffma2(a0, md0[2*q],     wq.x);
            ffma2(a1, md1[2*q],     wq.x);
            ffma2(a2, md0[2*q],     w2.x);
            ffma2(a3, md1[2*q],     w2.x);
            ffma2(a0, md0[2*q + 1], wq.y);
            ffma2(a1, md1[2*q + 1], wq.y);
            ffma2(a2, md0[2*q + 1], w2.y);
            ffma2(a3, md1[2*q + 1], w2.y);
        }
        float2 u0 = unpack2(a0), u1 = unpack2(a1);
        float2 u2 = unpack2(a2), u3 = unpack2(a3);
        float2 v0; v0.x = u0.x; v0.y = u1.x;
        float2 v1; v1.x = u0.y; v1.y = u1.y;
        float2 v2; v2.x = u2.x; v2.y = u3.x;
        float2 v3; v3.x = u2.y; v3.y = u3.y;
        *(float2*)(ob + (size_t)(2*fp)     * HWn) = v0;
        *(float2*)(ob + (size_t)(2*fp + 1) * HWn) = v1;
        *(float2*)(ob + (size_t)(2*fp + 2) * HWn) = v2;
        *(float2*)(ob + (size_t)(2*fp + 3) * HWn) = v3;
    }
}

// ---------------- launch ----------------
extern "C" void kernel_launch(void* const* d_in, const int* in_sizes, int n_in,
                              void* d_out, int out_size) {
    const float* features = (const float*)d_in[0];
    const float* carrier  = (const float*)d_in[1];
    const float* density  = (const float*)d_in[2];
    const float* w1 = (const float*)d_in[3];
    const float* b1 = (const float*)d_in[4];
    const float* w2 = (const float*)d_in[5];
    const float* b2 = (const float*)d_in[6];
    const float* w3 = (const float*)d_in[7];
    const float* b3 = (const float*)d_in[8];
    const float* w4 = (const float*)d_in[9];
    const float* b4 = (const float*)d_in[10];
    const float* proto = (const float*)d_in[11];
    float* outp = (float*)d_out;

    k_conv1<<<144, 256>>>(features, w1, b1);
    k_conv2<<<dim3(6, 6, 8), 256>>>(w2, b2);
    k_fused<<<Bn, 1024>>>(carrier, density, proto);
    k_final<<<576, 128>>>(w3, b3, w4, b4, outp);
}